// round 2
// baseline (speedup 1.0000x reference)
#include <cuda_runtime.h>

// ---------------- scratch (device globals; no allocation) ----------------
#define NMAX 50000
__device__ float g_h1 [NMAX * 128];   // x@W1, later reused as h2 (GAT transform)
__device__ float g_agg[NMAX * 128];   // aggregation buffer (GCN1 out, GAT out)
__device__ float g_inv[NMAX];         // deg -> rsqrt(deg)
__device__ float g_as [NMAX * 2];     // GAT a_src per (node, head)
__device__ float g_ad [NMAX * 2];     // GAT a_dst per (node, head)
__device__ float g_m  [NMAX * 2];     // segment max
__device__ float g_den[NMAX * 2];     // softmax denominator
__device__ float g_hx [NMAX * 64];    // elu(mean-head GAT) = GCN2 input
__device__ float g_h3 [NMAX * 64];    // hx @ W3

__device__ __forceinline__ float leaky(float v) { return v > 0.f ? v : 0.2f * v; }

__device__ __forceinline__ void atomicMaxF(float* a, float v) {
    if (v >= 0.f) atomicMax((int*)a, __float_as_int(v));
    else          atomicMin((unsigned int*)a, __float_as_uint(v));
}

// ---------------- degree ----------------
__global__ void k_deg_init(float* inv, int n) {
    int i = blockIdx.x * blockDim.x + threadIdx.x;
    if (i < n) inv[i] = 1.0f;                      // self loop
}
__global__ void k_deg_count(const int* __restrict__ dst, float* inv, int E) {
    int i = blockIdx.x * blockDim.x + threadIdx.x;
    if (i < E) atomicAdd(&inv[dst[i]], 1.0f);
}
__global__ void k_rsqrt(float* inv, int n) {
    int i = blockIdx.x * blockDim.x + threadIdx.x;
    if (i < n) inv[i] = rsqrtf(inv[i]);
}

// ---------------- GEMM: Y[n,P] = X[n,K] @ W[K,P] ----------------
template<int K, int P, int ROWS, int KT>
__global__ void gemm_kernel(const float* __restrict__ X, const float* __restrict__ W,
                            float* __restrict__ Y, int n)
{
    constexpr int NT = 128;
    constexpr int BX = P / 4;
    constexpr int BY = NT / BX;
    constexpr int RT = ROWS / BY;
    __shared__ __align__(16) float Ws[KT * P];
    __shared__ __align__(16) float Xs[ROWS * KT];

    int t  = threadIdx.x;
    int tx = t % BX, ty = t / BX;
    int r0 = blockIdx.x * ROWS;
    int rows = n - r0; if (rows > ROWS) rows = ROWS;

    float acc[RT][4];
    #pragma unroll
    for (int r = 0; r < RT; r++) { acc[r][0]=0.f; acc[r][1]=0.f; acc[r][2]=0.f; acc[r][3]=0.f; }

    for (int kt = 0; kt < K; kt += KT) {
        for (int i = t; i < KT * P; i += NT) Ws[i] = W[kt * P + i];
        for (int i = t; i < ROWS * KT; i += NT) {
            int r = i / KT, k = i % KT;
            Xs[i] = (r < rows) ? X[(size_t)(r0 + r) * K + kt + k] : 0.f;
        }
        __syncthreads();
        #pragma unroll 4
        for (int k = 0; k < KT; k++) {
            float4 w = *(const float4*)&Ws[k * P + tx * 4];
            #pragma unroll
            for (int r = 0; r < RT; r++) {
                float xv = Xs[(ty * RT + r) * KT + k];
                acc[r][0] += xv * w.x; acc[r][1] += xv * w.y;
                acc[r][2] += xv * w.z; acc[r][3] += xv * w.w;
            }
        }
        __syncthreads();
    }
    #pragma unroll
    for (int r = 0; r < RT; r++) {
        int row = ty * RT + r;
        if (row < rows)
            *(float4*)&Y[(size_t)(r0 + row) * P + tx * 4] =
                make_float4(acc[r][0], acc[r][1], acc[r][2], acc[r][3]);
    }
}

// ---------------- GCN: init (self loop + bias) and edge scatter ----------------
template<int F>
__global__ void k_gcn_init(const float* __restrict__ h, const float* __restrict__ inv,
                           const float* __restrict__ bias, float* __restrict__ out, int n)
{
    int i = blockIdx.x * blockDim.x + threadIdx.x;
    if (i >= n * F) return;
    int nn = i / F, f = i % F;
    float iv = inv[nn];
    out[i] = h[i] * iv * iv + bias[f];
}

template<int F>  // F = 128 or 64; one warp per edge
__global__ void k_gcn_edge(const float* __restrict__ h, const int* __restrict__ src,
                           const int* __restrict__ dst, const float* __restrict__ inv,
                           float* __restrict__ out, int E)
{
    int gid = blockIdx.x * blockDim.x + threadIdx.x;
    int e = gid >> 5, lane = gid & 31;
    if (e >= E) return;
    int s = src[e], d = dst[e];
    float c = inv[s] * inv[d];
    if (F == 128) {
        float4 v = *(const float4*)(h + (size_t)s * 128 + lane * 4);
        float* op = out + (size_t)d * 128 + lane * 4;
        atomicAdd(op + 0, v.x * c); atomicAdd(op + 1, v.y * c);
        atomicAdd(op + 2, v.z * c); atomicAdd(op + 3, v.w * c);
    } else {
        float2 v = *(const float2*)(h + (size_t)s * 64 + lane * 2);
        float* op = out + (size_t)d * 64 + lane * 2;
        atomicAdd(op + 0, v.x * c); atomicAdd(op + 1, v.y * c);
    }
}

__global__ void k_relu(float* a, int n) {
    int i = blockIdx.x * blockDim.x + threadIdx.x;
    if (i < n) a[i] = fmaxf(a[i], 0.f);
}

// ---------------- GAT ----------------
__global__ void k_gat_scores(const float* __restrict__ h2, const float* __restrict__ att_s,
                             const float* __restrict__ att_d, float* __restrict__ as_,
                             float* __restrict__ ad_, int n)
{
    int gid = blockIdx.x * blockDim.x + threadIdx.x;
    int w = gid >> 5, lane = gid & 31;
    if (w >= n * 2) return;
    int nn = w >> 1, hh = w & 1;
    const float* row = h2 + (size_t)nn * 128 + hh * 64;
    float v0 = row[lane], v1 = row[lane + 32];
    float s = v0 * att_s[hh * 64 + lane] + v1 * att_s[hh * 64 + lane + 32];
    float d = v0 * att_d[hh * 64 + lane] + v1 * att_d[hh * 64 + lane + 32];
    #pragma unroll
    for (int o = 16; o; o >>= 1) {
        s += __shfl_down_sync(0xffffffffu, s, o);
        d += __shfl_down_sync(0xffffffffu, d, o);
    }
    if (lane == 0) { as_[w] = s; ad_[w] = d; }
}

__global__ void k_gat_minit(const float* __restrict__ as_, const float* __restrict__ ad_,
                            float* __restrict__ m, int n2)
{
    int i = blockIdx.x * blockDim.x + threadIdx.x;
    if (i < n2) m[i] = leaky(as_[i] + ad_[i]);     // self-loop edge value
}

__global__ void k_gat_max(const int* __restrict__ src, const int* __restrict__ dst,
                          const float* __restrict__ as_, const float* __restrict__ ad_,
                          float* __restrict__ m, int E)
{
    int e = blockIdx.x * blockDim.x + threadIdx.x;
    if (e >= E) return;
    int s = src[e], d = dst[e];
    atomicMaxF(&m[d * 2 + 0], leaky(as_[s * 2 + 0] + ad_[d * 2 + 0]));
    atomicMaxF(&m[d * 2 + 1], leaky(as_[s * 2 + 1] + ad_[d * 2 + 1]));
}

__global__ void k_gat_deninit(const float* __restrict__ as_, const float* __restrict__ ad_,
                              const float* __restrict__ m, float* __restrict__ den, int n2)
{
    int i = blockIdx.x * blockDim.x + threadIdx.x;
    if (i < n2) den[i] = expf(leaky(as_[i] + ad_[i]) - m[i]);   // self-loop term
}

__global__ void k_gat_den(const int* __restrict__ src, const int* __restrict__ dst,
                          const float* __restrict__ as_, const float* __restrict__ ad_,
                          const float* __restrict__ m, float* __restrict__ den, int E)
{
    int e = blockIdx.x * blockDim.x + threadIdx.x;
    if (e >= E) return;
    int s = src[e], d = dst[e];
    atomicAdd(&den[d * 2 + 0], expf(leaky(as_[s * 2 + 0] + ad_[d * 2 + 0]) - m[d * 2 + 0]));
    atomicAdd(&den[d * 2 + 1], expf(leaky(as_[s * 2 + 1] + ad_[d * 2 + 1]) - m[d * 2 + 1]));
}

__global__ void k_gat_agginit(const float* __restrict__ h2, const float* __restrict__ as_,
                              const float* __restrict__ ad_, const float* __restrict__ m,
                              const float* __restrict__ den, float* __restrict__ out, int n)
{
    int i = blockIdx.x * blockDim.x + threadIdx.x;
    if (i >= n * 128) return;
    int nn = i >> 7, hh = (i >> 6) & 1;
    float es = leaky(as_[nn * 2 + hh] + ad_[nn * 2 + hh]);
    float alpha = expf(es - m[nn * 2 + hh]) / den[nn * 2 + hh];
    out[i] = h2[i] * alpha;
}

__global__ void k_gat_edge(const float* __restrict__ h2, const int* __restrict__ src,
                           const int* __restrict__ dst, const float* __restrict__ as_,
                           const float* __restrict__ ad_, const float* __restrict__ m,
                           const float* __restrict__ den, float* __restrict__ out, int E)
{
    int gid = blockIdx.x * blockDim.x + threadIdx.x;
    int e = gid >> 5, lane = gid & 31;
    if (e >= E) return;
    int s = src[e], d = dst[e];
    float e0 = leaky(as_[s * 2 + 0] + ad_[d * 2 + 0]);
    float e1 = leaky(as_[s * 2 + 1] + ad_[d * 2 + 1]);
    float a0 = expf(e0 - m[d * 2 + 0]) / den[d * 2 + 0];
    float a1 = expf(e1 - m[d * 2 + 1]) / den[d * 2 + 1];
    float c = (lane < 16) ? a0 : a1;            // features [0,64) = head0, [64,128) = head1
    float4 v = *(const float4*)(h2 + (size_t)s * 128 + lane * 4);
    float* op = out + (size_t)d * 128 + lane * 4;
    atomicAdd(op + 0, v.x * c); atomicAdd(op + 1, v.y * c);
    atomicAdd(op + 2, v.z * c); atomicAdd(op + 3, v.w * c);
}

__global__ void k_meanelu(const float* __restrict__ agg, const float* __restrict__ bg,
                          float* __restrict__ hx, int n)
{
    int i = blockIdx.x * blockDim.x + threadIdx.x;
    if (i >= n * 64) return;
    int nn = i >> 6, f = i & 63;
    float v = 0.5f * (agg[nn * 128 + f] + agg[nn * 128 + 64 + f]) + bg[f];
    hx[i] = v > 0.f ? v : expm1f(v);
}

// ---------------- host ----------------
static inline int up(int a, int b) { return (a + b - 1) / b; }

extern "C" void kernel_launch(void* const* d_in, const int* in_sizes, int n_in,
                              void* d_out, int out_size)
{
    const float* x       = (const float*)d_in[0];
    const int*   ei      = (const int*)d_in[1];    // int32! (JAX x64 disabled)
    const float* W1      = (const float*)d_in[2];
    const float* b1      = (const float*)d_in[3];
    const float* Wg      = (const float*)d_in[4];
    const float* att_src = (const float*)d_in[5];
    const float* att_dst = (const float*)d_in[6];
    const float* bg      = (const float*)d_in[7];
    const float* W3      = (const float*)d_in[8];
    const float* b3      = (const float*)d_in[9];
    float* out = (float*)d_out;

    int n = in_sizes[0] / 128;
    int E = in_sizes[1] / 2;
    const int* src = ei;
    const int* dst = ei + E;

    void* p;
    cudaGetSymbolAddress(&p, g_h1);  float* h1  = (float*)p;
    cudaGetSymbolAddress(&p, g_agg); float* agg = (float*)p;
    cudaGetSymbolAddress(&p, g_inv); float* inv = (float*)p;
    cudaGetSymbolAddress(&p, g_as);  float* as_ = (float*)p;
    cudaGetSymbolAddress(&p, g_ad);  float* ad_ = (float*)p;
    cudaGetSymbolAddress(&p, g_m);   float* m   = (float*)p;
    cudaGetSymbolAddress(&p, g_den); float* den = (float*)p;
    cudaGetSymbolAddress(&p, g_hx);  float* hx  = (float*)p;
    cudaGetSymbolAddress(&p, g_h3);  float* h3  = (float*)p;

    const int T = 256;

    // degrees (shared by all conv layers)
    k_deg_init <<<up(n, T), T>>>(inv, n);
    k_deg_count<<<up(E, T), T>>>(dst, inv, E);
    k_rsqrt    <<<up(n, T), T>>>(inv, n);

    // ---- GCN layer 1 ----
    gemm_kernel<128,128,32,64><<<up(n, 32), 128>>>(x, W1, h1, n);
    k_gcn_init<128><<<up(n * 128, T), T>>>(h1, inv, b1, agg, n);
    k_gcn_edge<128><<<up(E * 32, T), T>>>(h1, src, dst, inv, agg, E);
    k_relu<<<up(n * 128, T), T>>>(agg, n * 128);

    // ---- GAT layer ----
    gemm_kernel<128,128,32,64><<<up(n, 32), 128>>>(agg, Wg, h1, n);   // h2 in h1
    k_gat_scores <<<up(n * 64, T), T>>>(h1, att_src, att_dst, as_, ad_, n);
    k_gat_minit  <<<up(n * 2, T), T>>>(as_, ad_, m, n * 2);
    k_gat_max    <<<up(E, T), T>>>(src, dst, as_, ad_, m, E);
    k_gat_deninit<<<up(n * 2, T), T>>>(as_, ad_, m, den, n * 2);
    k_gat_den    <<<up(E, T), T>>>(src, dst, as_, ad_, m, den, E);
    k_gat_agginit<<<up(n * 128, T), T>>>(h1, as_, ad_, m, den, agg, n);
    k_gat_edge   <<<up(E * 32, T), T>>>(h1, src, dst, as_, ad_, m, den, agg, E);
    k_meanelu    <<<up(n * 64, T), T>>>(agg, bg, hx, n);

    // ---- GCN layer 2 ----
    gemm_kernel<64,64,32,64><<<up(n, 32), 128>>>(hx, W3, h3, n);
    k_gcn_init<64><<<up(n * 64, T), T>>>(h3, inv, b3, out, n);
    k_gcn_edge<64><<<up(E * 32, T), T>>>(h3, src, dst, inv, out, E);
}

// round 3
// speedup vs baseline: 1.6945x; 1.6945x over previous
#include <cuda_runtime.h>

// ---------------- scratch (device globals; no allocation) ----------------
#define NMAX 50000
__device__ float g_h1 [NMAX * 128];   // x@W1, later reused as h2 (GAT transform)
__device__ float g_agg[NMAX * 128];   // aggregation buffer (GCN1 out, GAT out)
__device__ float g_inv[NMAX];         // deg -> rsqrt(deg)
__device__ float g_as [NMAX * 2];     // GAT a_src per (node, head)
__device__ float g_ad [NMAX * 2];     // GAT a_dst per (node, head)
__device__ float g_m  [NMAX * 2];     // segment max
__device__ float g_den[NMAX * 2];     // softmax denominator
__device__ float g_hx [NMAX * 64];    // elu(mean-head GAT) = GCN2 input
__device__ float g_h3 [NMAX * 64];    // hx @ W3

__device__ __forceinline__ float leaky(float v) { return v > 0.f ? v : 0.2f * v; }

__device__ __forceinline__ void atomicMaxF(float* a, float v) {
    if (v >= 0.f) atomicMax((int*)a, __float_as_int(v));
    else          atomicMin((unsigned int*)a, __float_as_uint(v));
}

__device__ __forceinline__ void redAdd4(float* p, float a, float b, float c, float d) {
    asm volatile("red.global.add.v4.f32 [%0], {%1, %2, %3, %4};"
                 :: "l"(p), "f"(a), "f"(b), "f"(c), "f"(d) : "memory");
}
__device__ __forceinline__ void redAdd2(float* p, float a, float b) {
    asm volatile("red.global.add.v2.f32 [%0], {%1, %2};"
                 :: "l"(p), "f"(a), "f"(b) : "memory");
}

// ---------------- degree ----------------
__global__ void k_deg_init(float* inv, int n) {
    int i = blockIdx.x * blockDim.x + threadIdx.x;
    if (i < n) inv[i] = 1.0f;                      // self loop
}
__global__ void k_deg_count(const int* __restrict__ dst, float* inv, int E) {
    int i = blockIdx.x * blockDim.x + threadIdx.x;
    if (i < E) atomicAdd(&inv[dst[i]], 1.0f);
}
__global__ void k_rsqrt(float* inv, int n) {
    int i = blockIdx.x * blockDim.x + threadIdx.x;
    if (i < n) inv[i] = rsqrtf(inv[i]);
}

// ---------------- GEMM: Y[n,P] = X[n,K] @ W[K,P] ----------------
// RELU_LOAD: apply relu to X on smem fill.
// SELF_EPI:  also write out2 = Y*inv[row]^2 + bias (fused GCN self-loop init).
template<int K, int P, int ROWS, int KT, bool RELU_LOAD, bool SELF_EPI>
__global__ void gemm_kernel(const float* __restrict__ X, const float* __restrict__ W,
                            float* __restrict__ Y, const float* __restrict__ inv,
                            const float* __restrict__ bias, float* __restrict__ out2, int n)
{
    constexpr int NT = 128;
    constexpr int BX = P / 4;
    constexpr int BY = NT / BX;
    constexpr int RT = ROWS / BY;
    __shared__ __align__(16) float Ws[KT * P];
    __shared__ __align__(16) float Xs[ROWS * KT];

    int t  = threadIdx.x;
    int tx = t % BX, ty = t / BX;
    int r0 = blockIdx.x * ROWS;
    int rows = n - r0; if (rows > ROWS) rows = ROWS;

    float acc[RT][4];
    #pragma unroll
    for (int r = 0; r < RT; r++) { acc[r][0]=0.f; acc[r][1]=0.f; acc[r][2]=0.f; acc[r][3]=0.f; }

    for (int kt = 0; kt < K; kt += KT) {
        for (int i = t; i < KT * P; i += NT) Ws[i] = W[kt * P + i];
        for (int i = t; i < ROWS * KT; i += NT) {
            int r = i / KT, k = i % KT;
            float v = (r < rows) ? X[(size_t)(r0 + r) * K + kt + k] : 0.f;
            if (RELU_LOAD) v = fmaxf(v, 0.f);
            Xs[i] = v;
        }
        __syncthreads();
        #pragma unroll 4
        for (int k = 0; k < KT; k++) {
            float4 w = *(const float4*)&Ws[k * P + tx * 4];
            #pragma unroll
            for (int r = 0; r < RT; r++) {
                float xv = Xs[(ty * RT + r) * KT + k];
                acc[r][0] += xv * w.x; acc[r][1] += xv * w.y;
                acc[r][2] += xv * w.z; acc[r][3] += xv * w.w;
            }
        }
        __syncthreads();
    }
    float4 bv;
    if (SELF_EPI) bv = *(const float4*)&bias[tx * 4];
    #pragma unroll
    for (int r = 0; r < RT; r++) {
        int row = ty * RT + r;
        if (row < rows) {
            float4 y = make_float4(acc[r][0], acc[r][1], acc[r][2], acc[r][3]);
            *(float4*)&Y[(size_t)(r0 + row) * P + tx * 4] = y;
            if (SELF_EPI) {
                float iv = inv[r0 + row]; float c = iv * iv;
                *(float4*)&out2[(size_t)(r0 + row) * P + tx * 4] =
                    make_float4(y.x * c + bv.x, y.y * c + bv.y,
                                y.z * c + bv.z, y.w * c + bv.w);
            }
        }
    }
}

// ---------------- GCN edge scatter ----------------
// F=128: one warp per edge (float4 per lane). F=64: one warp per 2 edges.
__global__ void k_gcn_edge128(const float* __restrict__ h, const int* __restrict__ src,
                              const int* __restrict__ dst, const float* __restrict__ inv,
                              float* __restrict__ out, int E)
{
    int gid = blockIdx.x * blockDim.x + threadIdx.x;
    int e = gid >> 5, lane = gid & 31;
    if (e >= E) return;
    int s = src[e], d = dst[e];
    float c = inv[s] * inv[d];
    float4 v = *(const float4*)(h + (size_t)s * 128 + lane * 4);
    redAdd4(out + (size_t)d * 128 + lane * 4, v.x * c, v.y * c, v.z * c, v.w * c);
}

__global__ void k_gcn_edge64(const float* __restrict__ h, const int* __restrict__ src,
                             const int* __restrict__ dst, const float* __restrict__ inv,
                             float* __restrict__ out, int E)
{
    int gid = blockIdx.x * blockDim.x + threadIdx.x;
    int warp = gid >> 5, lane = gid & 31;
    int e = warp * 2 + (lane >> 4);
    if (e >= E) return;
    int sub = lane & 15;
    int s = src[e], d = dst[e];
    float c = inv[s] * inv[d];
    float4 v = *(const float4*)(h + (size_t)s * 64 + sub * 4);
    redAdd4(out + (size_t)d * 64 + sub * 4, v.x * c, v.y * c, v.z * c, v.w * c);
}

// ---------------- GAT ----------------
__global__ void k_gat_scores(const float* __restrict__ h2, const float* __restrict__ att_s,
                             const float* __restrict__ att_d, float* __restrict__ as_,
                             float* __restrict__ ad_, int n)
{
    int gid = blockIdx.x * blockDim.x + threadIdx.x;
    int w = gid >> 5, lane = gid & 31;
    if (w >= n * 2) return;
    int nn = w >> 1, hh = w & 1;
    const float* row = h2 + (size_t)nn * 128 + hh * 64;
    float v0 = row[lane], v1 = row[lane + 32];
    float s = v0 * att_s[hh * 64 + lane] + v1 * att_s[hh * 64 + lane + 32];
    float d = v0 * att_d[hh * 64 + lane] + v1 * att_d[hh * 64 + lane + 32];
    #pragma unroll
    for (int o = 16; o; o >>= 1) {
        s += __shfl_down_sync(0xffffffffu, s, o);
        d += __shfl_down_sync(0xffffffffu, d, o);
    }
    if (lane == 0) { as_[w] = s; ad_[w] = d; }
}

__global__ void k_gat_minit(const float* __restrict__ as_, const float* __restrict__ ad_,
                            float* __restrict__ m, int n2)
{
    int i = blockIdx.x * blockDim.x + threadIdx.x;
    if (i < n2) m[i] = leaky(as_[i] + ad_[i]);     // self-loop edge value
}

__global__ void k_gat_max(const int* __restrict__ src, const int* __restrict__ dst,
                          const float* __restrict__ as_, const float* __restrict__ ad_,
                          float* __restrict__ m, int E)
{
    int e = blockIdx.x * blockDim.x + threadIdx.x;
    if (e >= E) return;
    int s = src[e], d = dst[e];
    float2 a = *(const float2*)(as_ + s * 2);
    float2 b = *(const float2*)(ad_ + d * 2);
    atomicMaxF(&m[d * 2 + 0], leaky(a.x + b.x));
    atomicMaxF(&m[d * 2 + 1], leaky(a.y + b.y));
}

__global__ void k_gat_deninit(const float* __restrict__ as_, const float* __restrict__ ad_,
                              const float* __restrict__ m, float* __restrict__ den, int n2)
{
    int i = blockIdx.x * blockDim.x + threadIdx.x;
    if (i < n2) den[i] = __expf(leaky(as_[i] + ad_[i]) - m[i]);   // self-loop term
}

__global__ void k_gat_den(const int* __restrict__ src, const int* __restrict__ dst,
                          const float* __restrict__ as_, const float* __restrict__ ad_,
                          const float* __restrict__ m, float* __restrict__ den, int E)
{
    int e = blockIdx.x * blockDim.x + threadIdx.x;
    if (e >= E) return;
    int s = src[e], d = dst[e];
    float2 a  = *(const float2*)(as_ + s * 2);
    float2 b  = *(const float2*)(ad_ + d * 2);
    float2 mm = *(const float2*)(m + d * 2);
    redAdd2(den + d * 2, __expf(leaky(a.x + b.x) - mm.x),
                         __expf(leaky(a.y + b.y) - mm.y));
}

__global__ void k_gat_agginit(const float* __restrict__ h2, const float* __restrict__ as_,
                              const float* __restrict__ ad_, const float* __restrict__ m,
                              const float* __restrict__ den, float* __restrict__ out, int n)
{
    int i = blockIdx.x * blockDim.x + threadIdx.x;
    if (i >= n * 128) return;
    int nn = i >> 7, hh = (i >> 6) & 1;
    float es = leaky(as_[nn * 2 + hh] + ad_[nn * 2 + hh]);
    float alpha = __fdividef(__expf(es - m[nn * 2 + hh]), den[nn * 2 + hh]);
    out[i] = h2[i] * alpha;
}

__global__ void k_gat_edge(const float* __restrict__ h2, const int* __restrict__ src,
                           const int* __restrict__ dst, const float* __restrict__ as_,
                           const float* __restrict__ ad_, const float* __restrict__ m,
                           const float* __restrict__ den, float* __restrict__ out, int E)
{
    int gid = blockIdx.x * blockDim.x + threadIdx.x;
    int e = gid >> 5, lane = gid & 31;
    if (e >= E) return;
    int s = src[e], d = dst[e];
    float2 a  = *(const float2*)(as_ + s * 2);
    float2 b  = *(const float2*)(ad_ + d * 2);
    float2 mm = *(const float2*)(m + d * 2);
    float2 dn = *(const float2*)(den + d * 2);
    float a0 = __fdividef(__expf(leaky(a.x + b.x) - mm.x), dn.x);
    float a1 = __fdividef(__expf(leaky(a.y + b.y) - mm.y), dn.y);
    float c = (lane < 16) ? a0 : a1;            // features [0,64) = head0, [64,128) = head1
    float4 v = *(const float4*)(h2 + (size_t)s * 128 + lane * 4);
    redAdd4(out + (size_t)d * 128 + lane * 4, v.x * c, v.y * c, v.z * c, v.w * c);
}

__global__ void k_meanelu(const float* __restrict__ agg, const float* __restrict__ bg,
                          float* __restrict__ hx, int n)
{
    int i = blockIdx.x * blockDim.x + threadIdx.x;
    if (i >= n * 64) return;
    int nn = i >> 6, f = i & 63;
    float v = 0.5f * (agg[nn * 128 + f] + agg[nn * 128 + 64 + f]) + bg[f];
    hx[i] = v > 0.f ? v : expm1f(v);
}

// ---------------- host ----------------
static inline int up(int a, int b) { return (a + b - 1) / b; }

extern "C" void kernel_launch(void* const* d_in, const int* in_sizes, int n_in,
                              void* d_out, int out_size)
{
    const float* x       = (const float*)d_in[0];
    const int*   ei      = (const int*)d_in[1];    // int32 (JAX x64 disabled)
    const float* W1      = (const float*)d_in[2];
    const float* b1      = (const float*)d_in[3];
    const float* Wg      = (const float*)d_in[4];
    const float* att_src = (const float*)d_in[5];
    const float* att_dst = (const float*)d_in[6];
    const float* bg      = (const float*)d_in[7];
    const float* W3      = (const float*)d_in[8];
    const float* b3      = (const float*)d_in[9];
    float* out = (float*)d_out;

    int n = in_sizes[0] / 128;
    int E = in_sizes[1] / 2;
    const int* src = ei;
    const int* dst = ei + E;

    void* p;
    cudaGetSymbolAddress(&p, g_h1);  float* h1  = (float*)p;
    cudaGetSymbolAddress(&p, g_agg); float* agg = (float*)p;
    cudaGetSymbolAddress(&p, g_inv); float* inv = (float*)p;
    cudaGetSymbolAddress(&p, g_as);  float* as_ = (float*)p;
    cudaGetSymbolAddress(&p, g_ad);  float* ad_ = (float*)p;
    cudaGetSymbolAddress(&p, g_m);   float* m   = (float*)p;
    cudaGetSymbolAddress(&p, g_den); float* den = (float*)p;
    cudaGetSymbolAddress(&p, g_hx);  float* hx  = (float*)p;
    cudaGetSymbolAddress(&p, g_h3);  float* h3  = (float*)p;

    const int T = 256;

    // degrees (shared by all conv layers)
    k_deg_init <<<up(n, T), T>>>(inv, n);
    k_deg_count<<<up(E, T), T>>>(dst, inv, E);
    k_rsqrt    <<<up(n, T), T>>>(inv, n);

    // ---- GCN layer 1 : agg = h1*inv^2 + b1 fused into GEMM epilogue ----
    gemm_kernel<128,128,32,64,false,true><<<up(n, 32), 128>>>(x, W1, h1, inv, b1, agg, n);
    k_gcn_edge128<<<up(E * 32, T), T>>>(h1, src, dst, inv, agg, E);

    // ---- GAT layer : relu fused into GEMM2 load ----
    gemm_kernel<128,128,32,64,true,false><<<up(n, 32), 128>>>(agg, Wg, h1, inv, b1, agg, n);
    k_gat_scores <<<up(n * 64, T), T>>>(h1, att_src, att_dst, as_, ad_, n);
    k_gat_minit  <<<up(n * 2, T), T>>>(as_, ad_, m, n * 2);
    k_gat_max    <<<up(E, T), T>>>(src, dst, as_, ad_, m, E);
    k_gat_deninit<<<up(n * 2, T), T>>>(as_, ad_, m, den, n * 2);
    k_gat_den    <<<up(E, T), T>>>(src, dst, as_, ad_, m, den, E);
    k_gat_agginit<<<up(n * 128, T), T>>>(h1, as_, ad_, m, den, agg, n);
    k_gat_edge   <<<up(E * 32, T), T>>>(h1, src, dst, as_, ad_, m, den, agg, E);
    k_meanelu    <<<up(n * 64, T), T>>>(agg, bg, hx, n);

    // ---- GCN layer 2 : out = h3*inv^2 + b3 fused into GEMM epilogue ----
    gemm_kernel<64,64,32,64,false,true><<<up(n, 32), 128>>>(hx, W3, h3, inv, b3, out, n);
    k_gcn_edge64<<<up(E * 16, T), T>>>(h3, src, dst, inv, out, E);
}

// round 4
// speedup vs baseline: 2.4845x; 1.4662x over previous
#include <cuda_runtime.h>

// ---------------- scratch (device globals; no allocation) ----------------
#define NMAX 50000
#define EMAX 800000
__device__ float g_h1 [NMAX * 128];   // x@W1, later h2 (GAT transform)
__device__ float g_agg[NMAX * 128];   // relu(GCN1) output
__device__ float g_inv[NMAX];         // rsqrt(deg)
__device__ float g_as [NMAX * 2];     // GAT a_src per (node, head)
__device__ float g_ad [NMAX * 2];     // GAT a_dst per (node, head)
__device__ float g_hx [NMAX * 64];    // elu(mean-head GAT) = GCN2 input
__device__ float g_h3 [NMAX * 64];    // hx @ W3
__device__ int   g_deg[NMAX];
__device__ int   g_off[NMAX + 1];
__device__ int   g_cur[NMAX];
__device__ int   g_srcs[EMAX];        // src ids bucketed by dst

__device__ __forceinline__ float leaky(float v) { return v > 0.f ? v : 0.2f * v; }

// ---------------- degree + CSR build ----------------
__global__ void k_zero_deg(int* deg, int n) {
    int i = blockIdx.x * blockDim.x + threadIdx.x;
    if (i < n) deg[i] = 0;
}
__global__ void k_deg_count(const int* __restrict__ dst, int* deg, int E) {
    int i = blockIdx.x * blockDim.x + threadIdx.x;
    if (i < E) atomicAdd(&deg[dst[i]], 1);
}
__global__ void k_inv(const int* __restrict__ deg, float* inv, int n) {
    int i = blockIdx.x * blockDim.x + threadIdx.x;
    if (i < n) inv[i] = rsqrtf((float)(deg[i] + 1));   // +1 self loop
}
// single-block exclusive scan of deg into off (off[n] = total)
__global__ void k_scan(const int* __restrict__ deg, int* off, int* cur, int n) {
    __shared__ int sums[1024];
    int t = threadIdx.x;
    int chunk = (n + 1023) / 1024;
    int lo = t * chunk, hi = min(lo + chunk, n);
    int s = 0;
    for (int i = lo; i < hi; i++) s += deg[i];
    sums[t] = s;
    __syncthreads();
    for (int o = 1; o < 1024; o <<= 1) {
        int u = (t >= o) ? sums[t - o] : 0;
        __syncthreads();
        sums[t] += u;
        __syncthreads();
    }
    int run = sums[t] - s;           // exclusive base for this chunk
    for (int i = lo; i < hi; i++) {
        off[i] = run; cur[i] = run;
        run += deg[i];
    }
    if (t == 1023) off[n] = sums[1023];
}
__global__ void k_fill(const int* __restrict__ src, const int* __restrict__ dst,
                       int* cur, int* srcs, int E) {
    int i = blockIdx.x * blockDim.x + threadIdx.x;
    if (i >= E) return;
    int pos = atomicAdd(&cur[dst[i]], 1);
    srcs[pos] = src[i];
}

// ---------------- GEMM: Y[n,P] = X[n,K] @ W[K,P] ----------------
template<int K, int P, int ROWS, int KT>
__global__ void gemm_kernel(const float* __restrict__ X, const float* __restrict__ W,
                            float* __restrict__ Y, int n)
{
    constexpr int NT = 128;
    constexpr int BX = P / 4;
    constexpr int BY = NT / BX;
    constexpr int RT = ROWS / BY;
    __shared__ __align__(16) float Ws[KT * P];
    __shared__ __align__(16) float Xs[ROWS * KT];

    int t  = threadIdx.x;
    int tx = t % BX, ty = t / BX;
    int r0 = blockIdx.x * ROWS;
    int rows = n - r0; if (rows > ROWS) rows = ROWS;

    float4 acc[RT];
    #pragma unroll
    for (int r = 0; r < RT; r++) acc[r] = make_float4(0.f, 0.f, 0.f, 0.f);

    for (int kt = 0; kt < K; kt += KT) {
        for (int i = t; i < KT * P / 4; i += NT)
            ((float4*)Ws)[i] = ((const float4*)(W + kt * P))[i];
        for (int i = t; i < ROWS * KT / 4; i += NT) {
            int r = i / (KT / 4), k = (i % (KT / 4)) * 4;
            float4 v = (r < rows) ? *(const float4*)&X[(size_t)(r0 + r) * K + kt + k]
                                  : make_float4(0.f, 0.f, 0.f, 0.f);
            ((float4*)Xs)[i] = v;
        }
        __syncthreads();
        #pragma unroll
        for (int k4 = 0; k4 < KT; k4 += 4) {
            float4 w0 = *(const float4*)&Ws[(k4 + 0) * P + tx * 4];
            float4 w1 = *(const float4*)&Ws[(k4 + 1) * P + tx * 4];
            float4 w2 = *(const float4*)&Ws[(k4 + 2) * P + tx * 4];
            float4 w3 = *(const float4*)&Ws[(k4 + 3) * P + tx * 4];
            #pragma unroll
            for (int r = 0; r < RT; r++) {
                float4 xv = *(const float4*)&Xs[(ty * RT + r) * KT + k4];
                acc[r].x += xv.x*w0.x + xv.y*w1.x + xv.z*w2.x + xv.w*w3.x;
                acc[r].y += xv.x*w0.y + xv.y*w1.y + xv.z*w2.y + xv.w*w3.y;
                acc[r].z += xv.x*w0.z + xv.y*w1.z + xv.z*w2.z + xv.w*w3.z;
                acc[r].w += xv.x*w0.w + xv.y*w1.w + xv.z*w2.w + xv.w*w3.w;
            }
        }
        __syncthreads();
    }
    #pragma unroll
    for (int r = 0; r < RT; r++) {
        int row = ty * RT + r;
        if (row < rows)
            *(float4*)&Y[(size_t)(r0 + row) * P + tx * 4] = acc[r];
    }
}

// ---------------- GCN1 pull-aggregation (F=128) + relu ----------------
// one warp per node: out[d] = relu( sum_s h[s]*inv[s]*inv[d] + h[d]*inv[d]^2 + b )
__global__ void k_gcn1_agg(const float* __restrict__ h, const int* __restrict__ off,
                           const int* __restrict__ srcs, const float* __restrict__ inv,
                           const float* __restrict__ bias, float* __restrict__ out, int n)
{
    int gid = blockIdx.x * blockDim.x + threadIdx.x;
    int d = gid >> 5, lane = gid & 31;
    if (d >= n) return;
    int beg = off[d], end = off[d + 1];
    float invd = inv[d];

    float4 sv = *(const float4*)(h + (size_t)d * 128 + lane * 4);
    float cs = invd * invd;
    float4 acc = make_float4(sv.x * cs, sv.y * cs, sv.z * cs, sv.w * cs);

    int i = beg;
    for (; i + 2 <= end; i += 2) {
        int s0 = srcs[i], s1 = srcs[i + 1];
        float c0 = inv[s0] * invd, c1 = inv[s1] * invd;
        float4 v0 = *(const float4*)(h + (size_t)s0 * 128 + lane * 4);
        float4 v1 = *(const float4*)(h + (size_t)s1 * 128 + lane * 4);
        acc.x += v0.x * c0 + v1.x * c1; acc.y += v0.y * c0 + v1.y * c1;
        acc.z += v0.z * c0 + v1.z * c1; acc.w += v0.w * c0 + v1.w * c1;
    }
    if (i < end) {
        int s = srcs[i];
        float c = inv[s] * invd;
        float4 v = *(const float4*)(h + (size_t)s * 128 + lane * 4);
        acc.x += v.x * c; acc.y += v.y * c; acc.z += v.z * c; acc.w += v.w * c;
    }
    float4 b = *(const float4*)&bias[lane * 4];
    acc.x = fmaxf(acc.x + b.x, 0.f); acc.y = fmaxf(acc.y + b.y, 0.f);
    acc.z = fmaxf(acc.z + b.z, 0.f); acc.w = fmaxf(acc.w + b.w, 0.f);
    *(float4*)(out + (size_t)d * 128 + lane * 4) = acc;
}

// ---------------- GAT scores ----------------
__global__ void k_gat_scores(const float* __restrict__ h2, const float* __restrict__ att_s,
                             const float* __restrict__ att_d, float* __restrict__ as_,
                             float* __restrict__ ad_, int n)
{
    int gid = blockIdx.x * blockDim.x + threadIdx.x;
    int w = gid >> 5, lane = gid & 31;
    if (w >= n * 2) return;
    int nn = w >> 1, hh = w & 1;
    const float* row = h2 + (size_t)nn * 128 + hh * 64;
    float v0 = row[lane], v1 = row[lane + 32];
    float s = v0 * att_s[hh * 64 + lane] + v1 * att_s[hh * 64 + lane + 32];
    float d = v0 * att_d[hh * 64 + lane] + v1 * att_d[hh * 64 + lane + 32];
    #pragma unroll
    for (int o = 16; o; o >>= 1) {
        s += __shfl_down_sync(0xffffffffu, s, o);
        d += __shfl_down_sync(0xffffffffu, d, o);
    }
    if (lane == 0) { as_[w] = s; ad_[w] = d; }
}

// ---------------- GAT fused softmax + aggregation + head-mean + elu ----------------
// one warp per node; writes hx[d, 64] directly
__global__ void k_gat_agg(const float* __restrict__ h2, const int* __restrict__ off,
                          const int* __restrict__ srcs, const float* __restrict__ as_,
                          const float* __restrict__ ad_, const float* __restrict__ bg,
                          float* __restrict__ hx, int n)
{
    int gid = blockIdx.x * blockDim.x + threadIdx.x;
    int d = gid >> 5, lane = gid & 31;
    if (d >= n) return;
    int beg = off[d], end = off[d + 1];

    float2 ad = *(const float2*)(ad_ + d * 2);
    float2 asd = *(const float2*)(as_ + d * 2);
    float e0s = leaky(asd.x + ad.x), e1s = leaky(asd.y + ad.y);

    // pass 1: max (lane-parallel over edges)
    float m0 = e0s, m1 = e1s;
    for (int i = beg + lane; i < end; i += 32) {
        float2 a = *(const float2*)(as_ + srcs[i] * 2);
        m0 = fmaxf(m0, leaky(a.x + ad.x));
        m1 = fmaxf(m1, leaky(a.y + ad.y));
    }
    #pragma unroll
    for (int o = 16; o; o >>= 1) {
        m0 = fmaxf(m0, __shfl_xor_sync(0xffffffffu, m0, o));
        m1 = fmaxf(m1, __shfl_xor_sync(0xffffffffu, m1, o));
    }
    // pass 2: denominator
    float den0 = 0.f, den1 = 0.f;
    for (int i = beg + lane; i < end; i += 32) {
        float2 a = *(const float2*)(as_ + srcs[i] * 2);
        den0 += __expf(leaky(a.x + ad.x) - m0);
        den1 += __expf(leaky(a.y + ad.y) - m1);
    }
    #pragma unroll
    for (int o = 16; o; o >>= 1) {
        den0 += __shfl_xor_sync(0xffffffffu, den0, o);
        den1 += __shfl_xor_sync(0xffffffffu, den1, o);
    }
    den0 += __expf(e0s - m0);
    den1 += __expf(e1s - m1);
    float r0 = __fdividef(1.f, den0), r1 = __fdividef(1.f, den1);

    // pass 3: feature aggregation (serial edges, 32 lanes over 128 feats)
    float als = (lane < 16) ? __expf(e0s - m0) * r0 : __expf(e1s - m1) * r1;
    float4 sv = *(const float4*)(h2 + (size_t)d * 128 + lane * 4);
    float4 acc = make_float4(sv.x * als, sv.y * als, sv.z * als, sv.w * als);
    int i = beg;
    for (; i + 2 <= end; i += 2) {
        int s0 = srcs[i], s1 = srcs[i + 1];
        float2 a0 = *(const float2*)(as_ + s0 * 2);
        float2 a1 = *(const float2*)(as_ + s1 * 2);
        float c0 = (lane < 16) ? __expf(leaky(a0.x + ad.x) - m0) * r0
                               : __expf(leaky(a0.y + ad.y) - m1) * r1;
        float c1 = (lane < 16) ? __expf(leaky(a1.x + ad.x) - m0) * r0
                               : __expf(leaky(a1.y + ad.y) - m1) * r1;
        float4 v0 = *(const float4*)(h2 + (size_t)s0 * 128 + lane * 4);
        float4 v1 = *(const float4*)(h2 + (size_t)s1 * 128 + lane * 4);
        acc.x += v0.x * c0 + v1.x * c1; acc.y += v0.y * c0 + v1.y * c1;
        acc.z += v0.z * c0 + v1.z * c1; acc.w += v0.w * c0 + v1.w * c1;
    }
    if (i < end) {
        int s = srcs[i];
        float2 a = *(const float2*)(as_ + s * 2);
        float c = (lane < 16) ? __expf(leaky(a.x + ad.x) - m0) * r0
                              : __expf(leaky(a.y + ad.y) - m1) * r1;
        float4 v = *(const float4*)(h2 + (size_t)s * 128 + lane * 4);
        acc.x += v.x * c; acc.y += v.y * c; acc.z += v.z * c; acc.w += v.w * c;
    }
    // head mean + bias + elu: lane l (<16) pairs with lane l+16
    float ox = __shfl_down_sync(0xffffffffu, acc.x, 16);
    float oy = __shfl_down_sync(0xffffffffu, acc.y, 16);
    float oz = __shfl_down_sync(0xffffffffu, acc.z, 16);
    float ow = __shfl_down_sync(0xffffffffu, acc.w, 16);
    if (lane < 16) {
        float4 b = *(const float4*)&bg[lane * 4];
        float4 r;
        r.x = 0.5f * (acc.x + ox) + b.x;
        r.y = 0.5f * (acc.y + oy) + b.y;
        r.z = 0.5f * (acc.z + oz) + b.z;
        r.w = 0.5f * (acc.w + ow) + b.w;
        r.x = r.x > 0.f ? r.x : expm1f(r.x);
        r.y = r.y > 0.f ? r.y : expm1f(r.y);
        r.z = r.z > 0.f ? r.z : expm1f(r.z);
        r.w = r.w > 0.f ? r.w : expm1f(r.w);
        *(float4*)(hx + (size_t)d * 64 + lane * 4) = r;
    }
}

// ---------------- GCN2 pull-aggregation (F=64) ----------------
__global__ void k_gcn2_agg(const float* __restrict__ h, const int* __restrict__ off,
                           const int* __restrict__ srcs, const float* __restrict__ inv,
                           const float* __restrict__ bias, float* __restrict__ out, int n)
{
    int gid = blockIdx.x * blockDim.x + threadIdx.x;
    int d = gid >> 5, lane = gid & 31;
    if (d >= n) return;
    int beg = off[d], end = off[d + 1];
    float invd = inv[d];

    float2 sv = *(const float2*)(h + (size_t)d * 64 + lane * 2);
    float cs = invd * invd;
    float2 acc = make_float2(sv.x * cs, sv.y * cs);

    int i = beg;
    for (; i + 2 <= end; i += 2) {
        int s0 = srcs[i], s1 = srcs[i + 1];
        float c0 = inv[s0] * invd, c1 = inv[s1] * invd;
        float2 v0 = *(const float2*)(h + (size_t)s0 * 64 + lane * 2);
        float2 v1 = *(const float2*)(h + (size_t)s1 * 64 + lane * 2);
        acc.x += v0.x * c0 + v1.x * c1;
        acc.y += v0.y * c0 + v1.y * c1;
    }
    if (i < end) {
        int s = srcs[i];
        float c = inv[s] * invd;
        float2 v = *(const float2*)(h + (size_t)s * 64 + lane * 2);
        acc.x += v.x * c; acc.y += v.y * c;
    }
    float2 b = *(const float2*)&bias[lane * 2];
    *(float2*)(out + (size_t)d * 64 + lane * 2) = make_float2(acc.x + b.x, acc.y + b.y);
}

// ---------------- host ----------------
static inline int up(int a, int b) { return (a + b - 1) / b; }

extern "C" void kernel_launch(void* const* d_in, const int* in_sizes, int n_in,
                              void* d_out, int out_size)
{
    const float* x       = (const float*)d_in[0];
    const int*   ei      = (const int*)d_in[1];    // int32 (JAX x64 disabled)
    const float* W1      = (const float*)d_in[2];
    const float* b1      = (const float*)d_in[3];
    const float* Wg      = (const float*)d_in[4];
    const float* att_src = (const float*)d_in[5];
    const float* att_dst = (const float*)d_in[6];
    const float* bg      = (const float*)d_in[7];
    const float* W3      = (const float*)d_in[8];
    const float* b3      = (const float*)d_in[9];
    float* out = (float*)d_out;

    int n = in_sizes[0] / 128;
    int E = in_sizes[1] / 2;
    const int* src = ei;
    const int* dst = ei + E;

    void* p;
    cudaGetSymbolAddress(&p, g_h1);   float* h1   = (float*)p;
    cudaGetSymbolAddress(&p, g_agg);  float* agg  = (float*)p;
    cudaGetSymbolAddress(&p, g_inv);  float* inv  = (float*)p;
    cudaGetSymbolAddress(&p, g_as);   float* as_  = (float*)p;
    cudaGetSymbolAddress(&p, g_ad);   float* ad_  = (float*)p;
    cudaGetSymbolAddress(&p, g_hx);   float* hx   = (float*)p;
    cudaGetSymbolAddress(&p, g_h3);   float* h3   = (float*)p;
    cudaGetSymbolAddress(&p, g_deg);  int*   deg  = (int*)p;
    cudaGetSymbolAddress(&p, g_off);  int*   off  = (int*)p;
    cudaGetSymbolAddress(&p, g_cur);  int*   cur  = (int*)p;
    cudaGetSymbolAddress(&p, g_srcs); int*   srcs = (int*)p;

    const int T = 256;

    // CSR build (overlaps conceptually with GEMM1, launched first for deps)
    k_zero_deg <<<up(n, T), T>>>(deg, n);
    k_deg_count<<<up(E, T), T>>>(dst, deg, E);
    k_inv      <<<up(n, T), T>>>(deg, inv, n);
    k_scan     <<<1, 1024>>>(deg, off, cur, n);
    k_fill     <<<up(E, T), T>>>(src, dst, cur, srcs, E);

    // ---- GCN layer 1 ----
    gemm_kernel<128,128,32,64><<<up(n, 32), 128>>>(x, W1, h1, n);
    k_gcn1_agg<<<up(n * 32, T), T>>>(h1, off, srcs, inv, b1, agg, n);

    // ---- GAT layer ----
    gemm_kernel<128,128,32,64><<<up(n, 32), 128>>>(agg, Wg, h1, n);   // h2 in h1
    k_gat_scores<<<up(n * 64, T), T>>>(h1, att_src, att_dst, as_, ad_, n);
    k_gat_agg   <<<up(n * 32, T), T>>>(h1, off, srcs, as_, ad_, bg, hx, n);

    // ---- GCN layer 2 ----
    gemm_kernel<64,64,32,64><<<up(n, 32), 128>>>(hx, W3, h3, n);
    k_gcn2_agg<<<up(n * 32, T), T>>>(h3, off, srcs, inv, b3, out, n);
}

// round 5
// speedup vs baseline: 3.2178x; 1.2952x over previous
#include <cuda_runtime.h>

// ---------------- scratch (device globals; no allocation) ----------------
#define NMAX 50000
#define EMAX 800000
__device__ float g_h1 [NMAX * 128];   // x@W1, later h2 (GAT transform)
__device__ float g_agg[NMAX * 128];   // relu(GCN1) output
__device__ float g_inv[NMAX];         // rsqrt(deg)
__device__ float g_as [NMAX * 2];     // GAT a_src per (node, head)
__device__ float g_ad [NMAX * 2];     // GAT a_dst per (node, head)
__device__ float g_hx [NMAX * 64];    // elu(mean-head GAT) = GCN2 input
__device__ float g_h3 [NMAX * 64];    // hx @ W3
__device__ int   g_deg[NMAX];
__device__ int   g_off[NMAX];
__device__ int   g_cur[NMAX];
__device__ int   g_srcs[EMAX];        // src ids bucketed by dst
__device__ unsigned g_total;

__device__ __forceinline__ float leaky(float v) { return v > 0.f ? v : 0.2f * v; }

// ---------------- degree + CSR build ----------------
__global__ void k_zero_deg(int* deg, unsigned* total, int n) {
    int i = blockIdx.x * blockDim.x + threadIdx.x;
    if (i < n) deg[i] = 0;
    if (i == 0) *total = 0u;
}
__global__ void k_deg_count(const int* __restrict__ dst, int* deg, int E) {
    int i = blockIdx.x * blockDim.x + threadIdx.x;
    if (i < E) atomicAdd(&deg[dst[i]], 1);
}
__global__ void k_inv(const int* __restrict__ deg, float* inv, int n) {
    int i = blockIdx.x * blockDim.x + threadIdx.x;
    if (i < n) inv[i] = rsqrtf((float)(deg[i] + 1));   // +1 self loop
}
// parallel offset assignment: warp-scan + one atomic per warp on a cursor.
// Bucket placement order is arbitrary (irrelevant for correctness).
__global__ void k_offsets(const int* __restrict__ deg, int* off, int* cur,
                          unsigned* total, int n) {
    int i = blockIdx.x * blockDim.x + threadIdx.x;
    int lane = threadIdx.x & 31;
    int d = (i < n) ? deg[i] : 0;
    int x = d;                                   // inclusive warp scan
    #pragma unroll
    for (int o = 1; o < 32; o <<= 1) {
        int y = __shfl_up_sync(0xffffffffu, x, o);
        if (lane >= o) x += y;
    }
    int wsum = __shfl_sync(0xffffffffu, x, 31);
    unsigned base = 0;
    if (lane == 31) base = atomicAdd(total, (unsigned)wsum);
    base = __shfl_sync(0xffffffffu, base, 31);
    int excl = (int)base + x - d;
    if (i < n) { off[i] = excl; cur[i] = excl; }
}
__global__ void k_fill(const int* __restrict__ src, const int* __restrict__ dst,
                       int* cur, int* srcs, int E) {
    int i = blockIdx.x * blockDim.x + threadIdx.x;
    if (i >= E) return;
    int pos = atomicAdd(&cur[dst[i]], 1);
    srcs[pos] = src[i];
}

// ---------------- GEMM: Y[n,P] = X[n,K] @ W[K,P] ----------------
template<int K, int P, int ROWS, int KT>
__global__ void __launch_bounds__(128)
gemm_kernel(const float* __restrict__ X, const float* __restrict__ W,
            float* __restrict__ Y, int n)
{
    constexpr int NT = 128;
    constexpr int BX = P / 4;
    constexpr int BY = NT / BX;
    constexpr int RT = ROWS / BY;
    __shared__ __align__(16) float Ws[KT * P];
    __shared__ __align__(16) float Xs[ROWS * KT];

    int t  = threadIdx.x;
    int tx = t % BX, ty = t / BX;
    int r0 = blockIdx.x * ROWS;
    int rows = n - r0; if (rows > ROWS) rows = ROWS;

    float4 acc[RT];
    #pragma unroll
    for (int r = 0; r < RT; r++) acc[r] = make_float4(0.f, 0.f, 0.f, 0.f);

    for (int kt = 0; kt < K; kt += KT) {
        #pragma unroll
        for (int i = t; i < KT * P / 4; i += NT)
            ((float4*)Ws)[i] = ((const float4*)(W + kt * P))[i];
        #pragma unroll
        for (int i = t; i < ROWS * KT / 4; i += NT) {
            int r = i / (KT / 4), k = (i % (KT / 4)) * 4;
            float4 v = (r < rows) ? *(const float4*)&X[(size_t)(r0 + r) * K + kt + k]
                                  : make_float4(0.f, 0.f, 0.f, 0.f);
            ((float4*)Xs)[i] = v;
        }
        __syncthreads();
        #pragma unroll
        for (int k4 = 0; k4 < KT; k4 += 4) {
            float4 w0 = *(const float4*)&Ws[(k4 + 0) * P + tx * 4];
            float4 w1 = *(const float4*)&Ws[(k4 + 1) * P + tx * 4];
            float4 w2 = *(const float4*)&Ws[(k4 + 2) * P + tx * 4];
            float4 w3 = *(const float4*)&Ws[(k4 + 3) * P + tx * 4];
            #pragma unroll
            for (int r = 0; r < RT; r++) {
                float4 xv = *(const float4*)&Xs[(ty * RT + r) * KT + k4];
                acc[r].x += xv.x*w0.x + xv.y*w1.x + xv.z*w2.x + xv.w*w3.x;
                acc[r].y += xv.x*w0.y + xv.y*w1.y + xv.z*w2.y + xv.w*w3.y;
                acc[r].z += xv.x*w0.z + xv.y*w1.z + xv.z*w2.z + xv.w*w3.z;
                acc[r].w += xv.x*w0.w + xv.y*w1.w + xv.z*w2.w + xv.w*w3.w;
            }
        }
        __syncthreads();
    }
    #pragma unroll
    for (int r = 0; r < RT; r++) {
        int row = ty * RT + r;
        if (row < rows)
            *(float4*)&Y[(size_t)(r0 + row) * P + tx * 4] = acc[r];
    }
}

// ---------------- GCN1 pull-aggregation (F=128) + relu ----------------
__global__ void k_gcn1_agg(const float* __restrict__ h, const int* __restrict__ off,
                           const int* __restrict__ deg, const int* __restrict__ srcs,
                           const float* __restrict__ inv, const float* __restrict__ bias,
                           float* __restrict__ out, int n)
{
    int gid = blockIdx.x * blockDim.x + threadIdx.x;
    int d = gid >> 5, lane = gid & 31;
    if (d >= n) return;
    int beg = off[d], end = beg + deg[d];
    float invd = inv[d];

    float4 sv = *(const float4*)(h + (size_t)d * 128 + lane * 4);
    float cs = invd * invd;
    float4 acc = make_float4(sv.x * cs, sv.y * cs, sv.z * cs, sv.w * cs);

    int i = beg;
    for (; i + 2 <= end; i += 2) {
        int s0 = srcs[i], s1 = srcs[i + 1];
        float c0 = inv[s0] * invd, c1 = inv[s1] * invd;
        float4 v0 = *(const float4*)(h + (size_t)s0 * 128 + lane * 4);
        float4 v1 = *(const float4*)(h + (size_t)s1 * 128 + lane * 4);
        acc.x += v0.x * c0 + v1.x * c1; acc.y += v0.y * c0 + v1.y * c1;
        acc.z += v0.z * c0 + v1.z * c1; acc.w += v0.w * c0 + v1.w * c1;
    }
    if (i < end) {
        int s = srcs[i];
        float c = inv[s] * invd;
        float4 v = *(const float4*)(h + (size_t)s * 128 + lane * 4);
        acc.x += v.x * c; acc.y += v.y * c; acc.z += v.z * c; acc.w += v.w * c;
    }
    float4 b = *(const float4*)&bias[lane * 4];
    acc.x = fmaxf(acc.x + b.x, 0.f); acc.y = fmaxf(acc.y + b.y, 0.f);
    acc.z = fmaxf(acc.z + b.z, 0.f); acc.w = fmaxf(acc.w + b.w, 0.f);
    *(float4*)(out + (size_t)d * 128 + lane * 4) = acc;
}

// ---------------- GAT scores ----------------
__global__ void k_gat_scores(const float* __restrict__ h2, const float* __restrict__ att_s,
                             const float* __restrict__ att_d, float* __restrict__ as_,
                             float* __restrict__ ad_, int n)
{
    int gid = blockIdx.x * blockDim.x + threadIdx.x;
    int w = gid >> 5, lane = gid & 31;
    if (w >= n * 2) return;
    int nn = w >> 1, hh = w & 1;
    const float* row = h2 + (size_t)nn * 128 + hh * 64;
    float v0 = row[lane], v1 = row[lane + 32];
    float s = v0 * att_s[hh * 64 + lane] + v1 * att_s[hh * 64 + lane + 32];
    float d = v0 * att_d[hh * 64 + lane] + v1 * att_d[hh * 64 + lane + 32];
    #pragma unroll
    for (int o = 16; o; o >>= 1) {
        s += __shfl_down_sync(0xffffffffu, s, o);
        d += __shfl_down_sync(0xffffffffu, d, o);
    }
    if (lane == 0) { as_[w] = s; ad_[w] = d; }
}

// ---------------- GAT fused softmax + aggregation + head-mean + elu ----------------
__global__ void k_gat_agg(const float* __restrict__ h2, const int* __restrict__ off,
                          const int* __restrict__ deg, const int* __restrict__ srcs,
                          const float* __restrict__ as_, const float* __restrict__ ad_,
                          const float* __restrict__ bg, float* __restrict__ hx, int n)
{
    int gid = blockIdx.x * blockDim.x + threadIdx.x;
    int d = gid >> 5, lane = gid & 31;
    if (d >= n) return;
    int beg = off[d], end = beg + deg[d];

    float2 ad = *(const float2*)(ad_ + d * 2);
    float2 asd = *(const float2*)(as_ + d * 2);
    float e0s = leaky(asd.x + ad.x), e1s = leaky(asd.y + ad.y);

    // pass 1: max (lane-parallel over edges)
    float m0 = e0s, m1 = e1s;
    for (int i = beg + lane; i < end; i += 32) {
        float2 a = *(const float2*)(as_ + srcs[i] * 2);
        m0 = fmaxf(m0, leaky(a.x + ad.x));
        m1 = fmaxf(m1, leaky(a.y + ad.y));
    }
    #pragma unroll
    for (int o = 16; o; o >>= 1) {
        m0 = fmaxf(m0, __shfl_xor_sync(0xffffffffu, m0, o));
        m1 = fmaxf(m1, __shfl_xor_sync(0xffffffffu, m1, o));
    }
    // pass 2: denominator
    float den0 = 0.f, den1 = 0.f;
    for (int i = beg + lane; i < end; i += 32) {
        float2 a = *(const float2*)(as_ + srcs[i] * 2);
        den0 += __expf(leaky(a.x + ad.x) - m0);
        den1 += __expf(leaky(a.y + ad.y) - m1);
    }
    #pragma unroll
    for (int o = 16; o; o >>= 1) {
        den0 += __shfl_xor_sync(0xffffffffu, den0, o);
        den1 += __shfl_xor_sync(0xffffffffu, den1, o);
    }
    den0 += __expf(e0s - m0);
    den1 += __expf(e1s - m1);
    float r0 = __fdividef(1.f, den0), r1 = __fdividef(1.f, den1);

    // pass 3: feature aggregation (serial edges, 32 lanes over 128 feats)
    float als = (lane < 16) ? __expf(e0s - m0) * r0 : __expf(e1s - m1) * r1;
    float4 sv = *(const float4*)(h2 + (size_t)d * 128 + lane * 4);
    float4 acc = make_float4(sv.x * als, sv.y * als, sv.z * als, sv.w * als);
    int i = beg;
    for (; i + 2 <= end; i += 2) {
        int s0 = srcs[i], s1 = srcs[i + 1];
        float2 a0 = *(const float2*)(as_ + s0 * 2);
        float2 a1 = *(const float2*)(as_ + s1 * 2);
        float c0 = (lane < 16) ? __expf(leaky(a0.x + ad.x) - m0) * r0
                               : __expf(leaky(a0.y + ad.y) - m1) * r1;
        float c1 = (lane < 16) ? __expf(leaky(a1.x + ad.x) - m0) * r0
                               : __expf(leaky(a1.y + ad.y) - m1) * r1;
        float4 v0 = *(const float4*)(h2 + (size_t)s0 * 128 + lane * 4);
        float4 v1 = *(const float4*)(h2 + (size_t)s1 * 128 + lane * 4);
        acc.x += v0.x * c0 + v1.x * c1; acc.y += v0.y * c0 + v1.y * c1;
        acc.z += v0.z * c0 + v1.z * c1; acc.w += v0.w * c0 + v1.w * c1;
    }
    if (i < end) {
        int s = srcs[i];
        float2 a = *(const float2*)(as_ + s * 2);
        float c = (lane < 16) ? __expf(leaky(a.x + ad.x) - m0) * r0
                              : __expf(leaky(a.y + ad.y) - m1) * r1;
        float4 v = *(const float4*)(h2 + (size_t)s * 128 + lane * 4);
        acc.x += v.x * c; acc.y += v.y * c; acc.z += v.z * c; acc.w += v.w * c;
    }
    // head mean + bias + elu: lane l (<16) pairs with lane l+16
    float ox = __shfl_down_sync(0xffffffffu, acc.x, 16);
    float oy = __shfl_down_sync(0xffffffffu, acc.y, 16);
    float oz = __shfl_down_sync(0xffffffffu, acc.z, 16);
    float ow = __shfl_down_sync(0xffffffffu, acc.w, 16);
    if (lane < 16) {
        float4 b = *(const float4*)&bg[lane * 4];
        float4 r;
        r.x = 0.5f * (acc.x + ox) + b.x;
        r.y = 0.5f * (acc.y + oy) + b.y;
        r.z = 0.5f * (acc.z + oz) + b.z;
        r.w = 0.5f * (acc.w + ow) + b.w;
        r.x = r.x > 0.f ? r.x : expm1f(r.x);
        r.y = r.y > 0.f ? r.y : expm1f(r.y);
        r.z = r.z > 0.f ? r.z : expm1f(r.z);
        r.w = r.w > 0.f ? r.w : expm1f(r.w);
        *(float4*)(hx + (size_t)d * 64 + lane * 4) = r;
    }
}

// ---------------- GCN2 pull-aggregation (F=64) ----------------
__global__ void k_gcn2_agg(const float* __restrict__ h, const int* __restrict__ off,
                           const int* __restrict__ deg, const int* __restrict__ srcs,
                           const float* __restrict__ inv, const float* __restrict__ bias,
                           float* __restrict__ out, int n)
{
    int gid = blockIdx.x * blockDim.x + threadIdx.x;
    int d = gid >> 5, lane = gid & 31;
    if (d >= n) return;
    int beg = off[d], end = beg + deg[d];
    float invd = inv[d];

    float2 sv = *(const float2*)(h + (size_t)d * 64 + lane * 2);
    float cs = invd * invd;
    float2 acc = make_float2(sv.x * cs, sv.y * cs);

    int i = beg;
    for (; i + 2 <= end; i += 2) {
        int s0 = srcs[i], s1 = srcs[i + 1];
        float c0 = inv[s0] * invd, c1 = inv[s1] * invd;
        float2 v0 = *(const float2*)(h + (size_t)s0 * 64 + lane * 2);
        float2 v1 = *(const float2*)(h + (size_t)s1 * 64 + lane * 2);
        acc.x += v0.x * c0 + v1.x * c1;
        acc.y += v0.y * c0 + v1.y * c1;
    }
    if (i < end) {
        int s = srcs[i];
        float c = inv[s] * invd;
        float2 v = *(const float2*)(h + (size_t)s * 64 + lane * 2);
        acc.x += v.x * c; acc.y += v.y * c;
    }
    float2 b = *(const float2*)&bias[lane * 2];
    *(float2*)(out + (size_t)d * 64 + lane * 2) = make_float2(acc.x + b.x, acc.y + b.y);
}

// ---------------- host ----------------
static inline int up(int a, int b) { return (a + b - 1) / b; }

extern "C" void kernel_launch(void* const* d_in, const int* in_sizes, int n_in,
                              void* d_out, int out_size)
{
    const float* x       = (const float*)d_in[0];
    const int*   ei      = (const int*)d_in[1];    // int32 (JAX x64 disabled)
    const float* W1      = (const float*)d_in[2];
    const float* b1      = (const float*)d_in[3];
    const float* Wg      = (const float*)d_in[4];
    const float* att_src = (const float*)d_in[5];
    const float* att_dst = (const float*)d_in[6];
    const float* bg      = (const float*)d_in[7];
    const float* W3      = (const float*)d_in[8];
    const float* b3      = (const float*)d_in[9];
    float* out = (float*)d_out;

    int n = in_sizes[0] / 128;
    int E = in_sizes[1] / 2;
    const int* src = ei;
    const int* dst = ei + E;

    void* p;
    cudaGetSymbolAddress(&p, g_h1);   float* h1    = (float*)p;
    cudaGetSymbolAddress(&p, g_agg);  float* agg   = (float*)p;
    cudaGetSymbolAddress(&p, g_inv);  float* inv   = (float*)p;
    cudaGetSymbolAddress(&p, g_as);   float* as_   = (float*)p;
    cudaGetSymbolAddress(&p, g_ad);   float* ad_   = (float*)p;
    cudaGetSymbolAddress(&p, g_hx);   float* hx    = (float*)p;
    cudaGetSymbolAddress(&p, g_h3);   float* h3    = (float*)p;
    cudaGetSymbolAddress(&p, g_deg);  int*   deg   = (int*)p;
    cudaGetSymbolAddress(&p, g_off);  int*   off   = (int*)p;
    cudaGetSymbolAddress(&p, g_cur);  int*   cur   = (int*)p;
    cudaGetSymbolAddress(&p, g_srcs); int*   srcs  = (int*)p;
    cudaGetSymbolAddress(&p, g_total); unsigned* total = (unsigned*)p;

    const int T = 256;

    // CSR build
    k_zero_deg <<<up(n, T), T>>>(deg, total, n);
    k_deg_count<<<up(E, T), T>>>(dst, deg, E);
    k_inv      <<<up(n, T), T>>>(deg, inv, n);
    k_offsets  <<<up(n, T), T>>>(deg, off, cur, total, n);
    k_fill     <<<up(E, T), T>>>(src, dst, cur, srcs, E);

    // ---- GCN layer 1 ----
    gemm_kernel<128,128,64,32><<<up(n, 64), 128>>>(x, W1, h1, n);
    k_gcn1_agg<<<up(n * 32, T), T>>>(h1, off, deg, srcs, inv, b1, agg, n);

    // ---- GAT layer ----
    gemm_kernel<128,128,64,32><<<up(n, 64), 128>>>(agg, Wg, h1, n);   // h2 in h1
    k_gat_scores<<<up(n * 64, T), T>>>(h1, att_src, att_dst, as_, ad_, n);
    k_gat_agg   <<<up(n * 32, T), T>>>(h1, off, deg, srcs, as_, ad_, bg, hx, n);

    // ---- GCN layer 2 ----
    gemm_kernel<64,64,64,32><<<up(n, 64), 128>>>(hx, W3, h3, n);
    k_gcn2_agg<<<up(n * 32, T), T>>>(h3, off, deg, srcs, inv, b3, out, n);
}

// round 6
// speedup vs baseline: 3.4095x; 1.0596x over previous
#include <cuda_runtime.h>
#include <cstdint>

// ---------------- scratch (device globals; no allocation) ----------------
#define NMAX 50000
#define EMAX 800000
__device__ float g_h1 [NMAX * 128];   // x@W1, later h2 (GAT transform)
__device__ float g_agg[NMAX * 128];   // relu(GCN1) output
__device__ float g_inv[NMAX];         // rsqrt(deg)
__device__ float g_as [NMAX * 2];     // GAT a_src per (node, head)
__device__ float g_ad [NMAX * 2];     // GAT a_dst per (node, head)
__device__ float g_hx [NMAX * 64];    // elu(mean-head GAT) = GCN2 input
__device__ float g_h3 [NMAX * 64];    // hx @ W3
__device__ int   g_deg[NMAX];
__device__ int   g_off[NMAX];
__device__ int   g_cur[NMAX];
__device__ int   g_srcs[EMAX];        // src ids bucketed by dst
__device__ unsigned g_total;

__device__ __forceinline__ float leaky(float v) { return v > 0.f ? v : 0.2f * v; }

// ---------------- degree + CSR build ----------------
__global__ void k_zero_deg(int* deg, unsigned* total, int n) {
    int i = blockIdx.x * blockDim.x + threadIdx.x;
    if (i < n) deg[i] = 0;
    if (i == 0) *total = 0u;
}
__global__ void k_deg_count(const int* __restrict__ dst, int* deg, int E) {
    int i = blockIdx.x * blockDim.x + threadIdx.x;
    if (i < E) atomicAdd(&deg[dst[i]], 1);
}
__global__ void k_inv(const int* __restrict__ deg, float* inv, int n) {
    int i = blockIdx.x * blockDim.x + threadIdx.x;
    if (i < n) inv[i] = rsqrtf((float)(deg[i] + 1));   // +1 self loop
}
// parallel offset assignment: warp-scan + one atomic per warp on a cursor.
__global__ void k_offsets(const int* __restrict__ deg, int* off, int* cur,
                          unsigned* total, int n) {
    int i = blockIdx.x * blockDim.x + threadIdx.x;
    int lane = threadIdx.x & 31;
    int d = (i < n) ? deg[i] : 0;
    int x = d;
    #pragma unroll
    for (int o = 1; o < 32; o <<= 1) {
        int y = __shfl_up_sync(0xffffffffu, x, o);
        if (lane >= o) x += y;
    }
    int wsum = __shfl_sync(0xffffffffu, x, 31);
    unsigned base = 0;
    if (lane == 31) base = atomicAdd(total, (unsigned)wsum);
    base = __shfl_sync(0xffffffffu, base, 31);
    int excl = (int)base + x - d;
    if (i < n) { off[i] = excl; cur[i] = excl; }
}
__global__ void k_fill(const int* __restrict__ src, const int* __restrict__ dst,
                       int* cur, int* srcs, int E) {
    int i = blockIdx.x * blockDim.x + threadIdx.x;
    if (i >= E) return;
    int pos = atomicAdd(&cur[dst[i]], 1);
    srcs[pos] = src[i];
}

// ---------------- TF32 tensor-core GEMM with error compensation ----------------
// Y[n,P] = X[n,K] @ W[K,P]. Each value split x = hi + lo (tf32); per tile do
// hi*hi + hi*lo + lo*hi (fp32 accum) -> ~2^-22 error, fp32-grade accuracy.
__device__ __forceinline__ void split_tf32(float x, uint32_t& hi, uint32_t& lo) {
    uint32_t h;
    asm("cvt.rna.tf32.f32 %0, %1;" : "=r"(h) : "f"(x));
    float l = x - __uint_as_float(h);
    uint32_t lw;
    asm("cvt.rna.tf32.f32 %0, %1;" : "=r"(lw) : "f"(l));
    hi = h; lo = lw;
}
__device__ __forceinline__ void mma_tf32(float* c, const uint32_t* a, const uint32_t* b) {
    asm volatile("mma.sync.aligned.m16n8k8.row.col.f32.tf32.tf32.f32 "
        "{%0,%1,%2,%3},{%4,%5,%6,%7},{%8,%9},{%0,%1,%2,%3};"
        : "+f"(c[0]), "+f"(c[1]), "+f"(c[2]), "+f"(c[3])
        : "r"(a[0]), "r"(a[1]), "r"(a[2]), "r"(a[3]), "r"(b[0]), "r"(b[1]));
}

template<int K, int P>
__global__ void __launch_bounds__(256)
gemm_tf32(const float* __restrict__ X, const float* __restrict__ W,
          float* __restrict__ Y, int n)
{
    constexpr int BM = 128;
    constexpr int BK = 32;
    constexpr int WARPS_N = P / 64;          // 2 (P=128) or 1 (P=64)
    constexpr int WARPS_M = 8 / WARPS_N;     // 4 or 8
    constexpr int WM = BM / WARPS_M;         // 32 or 16
    constexpr int MF = WM / 16;              // 2 or 1
    constexpr int NF = 8;                    // 64 cols / 8
    constexpr int XS = BK + 4;               // A pad: banks (4g+tg) distinct
    constexpr int WS = P + 8;                // B pad: banks (8*tg+g) distinct

    __shared__ __align__(16) float Xs[BM * XS];
    __shared__ __align__(16) float Ws[BK * WS];

    int tid = threadIdx.x;
    int wid = tid >> 5, lane = tid & 31;
    int wm = wid % WARPS_M, wn = wid / WARPS_M;
    int g = lane >> 2, tg = lane & 3;

    int r0 = blockIdx.x * BM;
    int rows = n - r0; if (rows > BM) rows = BM;

    float c[MF][NF][4];
    #pragma unroll
    for (int mf = 0; mf < MF; mf++)
        #pragma unroll
        for (int nf = 0; nf < NF; nf++)
            #pragma unroll
            for (int q = 0; q < 4; q++) c[mf][nf][q] = 0.f;

    for (int kt = 0; kt < K; kt += BK) {
        #pragma unroll
        for (int i = tid; i < BK * P / 4; i += 256) {
            int k = i / (P / 4), c4 = (i % (P / 4)) * 4;
            *(float4*)&Ws[k * WS + c4] = *(const float4*)&W[(kt + k) * P + c4];
        }
        #pragma unroll
        for (int i = tid; i < BM * BK / 4; i += 256) {
            int r = i / (BK / 4), k4 = (i % (BK / 4)) * 4;
            float4 v = (r < rows) ? *(const float4*)&X[(size_t)(r0 + r) * K + kt + k4]
                                  : make_float4(0.f, 0.f, 0.f, 0.f);
            *(float4*)&Xs[r * XS + k4] = v;
        }
        __syncthreads();
        #pragma unroll
        for (int k8 = 0; k8 < BK; k8 += 8) {
            uint32_t ah[MF][4], al[MF][4];
            #pragma unroll
            for (int mf = 0; mf < MF; mf++) {
                int rb = wm * WM + mf * 16;
                split_tf32(Xs[(rb + g    ) * XS + k8 + tg    ], ah[mf][0], al[mf][0]);
                split_tf32(Xs[(rb + g + 8) * XS + k8 + tg    ], ah[mf][1], al[mf][1]);
                split_tf32(Xs[(rb + g    ) * XS + k8 + tg + 4], ah[mf][2], al[mf][2]);
                split_tf32(Xs[(rb + g + 8) * XS + k8 + tg + 4], ah[mf][3], al[mf][3]);
            }
            uint32_t bh[NF][2], bl[NF][2];
            #pragma unroll
            for (int nf = 0; nf < NF; nf++) {
                int col = wn * 64 + nf * 8 + g;
                split_tf32(Ws[(k8 + tg    ) * WS + col], bh[nf][0], bl[nf][0]);
                split_tf32(Ws[(k8 + tg + 4) * WS + col], bh[nf][1], bl[nf][1]);
            }
            #pragma unroll
            for (int mf = 0; mf < MF; mf++)
                #pragma unroll
                for (int nf = 0; nf < NF; nf++) {
                    mma_tf32(c[mf][nf], ah[mf], bh[nf]);
                    mma_tf32(c[mf][nf], ah[mf], bl[nf]);
                    mma_tf32(c[mf][nf], al[mf], bh[nf]);
                }
        }
        __syncthreads();
    }
    // epilogue: c0,c1 -> (row g, cols 2tg,2tg+1); c2,c3 -> row g+8
    #pragma unroll
    for (int mf = 0; mf < MF; mf++) {
        int rb = wm * WM + mf * 16;
        #pragma unroll
        for (int nf = 0; nf < NF; nf++) {
            int col = wn * 64 + nf * 8 + 2 * tg;
            int ra = rb + g, rc = rb + g + 8;
            if (ra < rows)
                *(float2*)&Y[(size_t)(r0 + ra) * P + col] = make_float2(c[mf][nf][0], c[mf][nf][1]);
            if (rc < rows)
                *(float2*)&Y[(size_t)(r0 + rc) * P + col] = make_float2(c[mf][nf][2], c[mf][nf][3]);
        }
    }
}

// ---------------- GCN1 pull-aggregation (F=128) + relu ----------------
__global__ void k_gcn1_agg(const float* __restrict__ h, const int* __restrict__ off,
                           const int* __restrict__ deg, const int* __restrict__ srcs,
                           const float* __restrict__ inv, const float* __restrict__ bias,
                           float* __restrict__ out, int n)
{
    int gid = blockIdx.x * blockDim.x + threadIdx.x;
    int d = gid >> 5, lane = gid & 31;
    if (d >= n) return;
    int beg = off[d], end = beg + deg[d];
    float invd = inv[d];

    float4 sv = *(const float4*)(h + (size_t)d * 128 + lane * 4);
    float cs = invd * invd;
    float4 acc = make_float4(sv.x * cs, sv.y * cs, sv.z * cs, sv.w * cs);

    int i = beg;
    for (; i + 2 <= end; i += 2) {
        int s0 = srcs[i], s1 = srcs[i + 1];
        float c0 = inv[s0] * invd, c1 = inv[s1] * invd;
        float4 v0 = *(const float4*)(h + (size_t)s0 * 128 + lane * 4);
        float4 v1 = *(const float4*)(h + (size_t)s1 * 128 + lane * 4);
        acc.x += v0.x * c0 + v1.x * c1; acc.y += v0.y * c0 + v1.y * c1;
        acc.z += v0.z * c0 + v1.z * c1; acc.w += v0.w * c0 + v1.w * c1;
    }
    if (i < end) {
        int s = srcs[i];
        float c = inv[s] * invd;
        float4 v = *(const float4*)(h + (size_t)s * 128 + lane * 4);
        acc.x += v.x * c; acc.y += v.y * c; acc.z += v.z * c; acc.w += v.w * c;
    }
    float4 b = *(const float4*)&bias[lane * 4];
    acc.x = fmaxf(acc.x + b.x, 0.f); acc.y = fmaxf(acc.y + b.y, 0.f);
    acc.z = fmaxf(acc.z + b.z, 0.f); acc.w = fmaxf(acc.w + b.w, 0.f);
    *(float4*)(out + (size_t)d * 128 + lane * 4) = acc;
}

// ---------------- GAT scores ----------------
__global__ void k_gat_scores(const float* __restrict__ h2, const float* __restrict__ att_s,
                             const float* __restrict__ att_d, float* __restrict__ as_,
                             float* __restrict__ ad_, int n)
{
    int gid = blockIdx.x * blockDim.x + threadIdx.x;
    int w = gid >> 5, lane = gid & 31;
    if (w >= n * 2) return;
    int nn = w >> 1, hh = w & 1;
    const float* row = h2 + (size_t)nn * 128 + hh * 64;
    float v0 = row[lane], v1 = row[lane + 32];
    float s = v0 * att_s[hh * 64 + lane] + v1 * att_s[hh * 64 + lane + 32];
    float d = v0 * att_d[hh * 64 + lane] + v1 * att_d[hh * 64 + lane + 32];
    #pragma unroll
    for (int o = 16; o; o >>= 1) {
        s += __shfl_down_sync(0xffffffffu, s, o);
        d += __shfl_down_sync(0xffffffffu, d, o);
    }
    if (lane == 0) { as_[w] = s; ad_[w] = d; }
}

// ---------------- GAT fused softmax + aggregation + head-mean + elu ----------------
__global__ void k_gat_agg(const float* __restrict__ h2, const int* __restrict__ off,
                          const int* __restrict__ deg, const int* __restrict__ srcs,
                          const float* __restrict__ as_, const float* __restrict__ ad_,
                          const float* __restrict__ bg, float* __restrict__ hx, int n)
{
    int gid = blockIdx.x * blockDim.x + threadIdx.x;
    int d = gid >> 5, lane = gid & 31;
    if (d >= n) return;
    int beg = off[d], end = beg + deg[d];

    float2 ad = *(const float2*)(ad_ + d * 2);
    float2 asd = *(const float2*)(as_ + d * 2);
    float e0s = leaky(asd.x + ad.x), e1s = leaky(asd.y + ad.y);

    float m0 = e0s, m1 = e1s;
    for (int i = beg + lane; i < end; i += 32) {
        float2 a = *(const float2*)(as_ + srcs[i] * 2);
        m0 = fmaxf(m0, leaky(a.x + ad.x));
        m1 = fmaxf(m1, leaky(a.y + ad.y));
    }
    #pragma unroll
    for (int o = 16; o; o >>= 1) {
        m0 = fmaxf(m0, __shfl_xor_sync(0xffffffffu, m0, o));
        m1 = fmaxf(m1, __shfl_xor_sync(0xffffffffu, m1, o));
    }
    float den0 = 0.f, den1 = 0.f;
    for (int i = beg + lane; i < end; i += 32) {
        float2 a = *(const float2*)(as_ + srcs[i] * 2);
        den0 += __expf(leaky(a.x + ad.x) - m0);
        den1 += __expf(leaky(a.y + ad.y) - m1);
    }
    #pragma unroll
    for (int o = 16; o; o >>= 1) {
        den0 += __shfl_xor_sync(0xffffffffu, den0, o);
        den1 += __shfl_xor_sync(0xffffffffu, den1, o);
    }
    den0 += __expf(e0s - m0);
    den1 += __expf(e1s - m1);
    float r0 = __fdividef(1.f, den0), r1 = __fdividef(1.f, den1);

    float als = (lane < 16) ? __expf(e0s - m0) * r0 : __expf(e1s - m1) * r1;
    float4 sv = *(const float4*)(h2 + (size_t)d * 128 + lane * 4);
    float4 acc = make_float4(sv.x * als, sv.y * als, sv.z * als, sv.w * als);
    int i = beg;
    for (; i + 2 <= end; i += 2) {
        int s0 = srcs[i], s1 = srcs[i + 1];
        float2 a0 = *(const float2*)(as_ + s0 * 2);
        float2 a1 = *(const float2*)(as_ + s1 * 2);
        float c0 = (lane < 16) ? __expf(leaky(a0.x + ad.x) - m0) * r0
                               : __expf(leaky(a0.y + ad.y) - m1) * r1;
        float c1 = (lane < 16) ? __expf(leaky(a1.x + ad.x) - m0) * r0
                               : __expf(leaky(a1.y + ad.y) - m1) * r1;
        float4 v0 = *(const float4*)(h2 + (size_t)s0 * 128 + lane * 4);
        float4 v1 = *(const float4*)(h2 + (size_t)s1 * 128 + lane * 4);
        acc.x += v0.x * c0 + v1.x * c1; acc.y += v0.y * c0 + v1.y * c1;
        acc.z += v0.z * c0 + v1.z * c1; acc.w += v0.w * c0 + v1.w * c1;
    }
    if (i < end) {
        int s = srcs[i];
        float2 a = *(const float2*)(as_ + s * 2);
        float c = (lane < 16) ? __expf(leaky(a.x + ad.x) - m0) * r0
                              : __expf(leaky(a.y + ad.y) - m1) * r1;
        float4 v = *(const float4*)(h2 + (size_t)s * 128 + lane * 4);
        acc.x += v.x * c; acc.y += v.y * c; acc.z += v.z * c; acc.w += v.w * c;
    }
    float ox = __shfl_down_sync(0xffffffffu, acc.x, 16);
    float oy = __shfl_down_sync(0xffffffffu, acc.y, 16);
    float oz = __shfl_down_sync(0xffffffffu, acc.z, 16);
    float ow = __shfl_down_sync(0xffffffffu, acc.w, 16);
    if (lane < 16) {
        float4 b = *(const float4*)&bg[lane * 4];
        float4 r;
        r.x = 0.5f * (acc.x + ox) + b.x;
        r.y = 0.5f * (acc.y + oy) + b.y;
        r.z = 0.5f * (acc.z + oz) + b.z;
        r.w = 0.5f * (acc.w + ow) + b.w;
        r.x = r.x > 0.f ? r.x : expm1f(r.x);
        r.y = r.y > 0.f ? r.y : expm1f(r.y);
        r.z = r.z > 0.f ? r.z : expm1f(r.z);
        r.w = r.w > 0.f ? r.w : expm1f(r.w);
        *(float4*)(hx + (size_t)d * 64 + lane * 4) = r;
    }
}

// ---------------- GCN2 pull-aggregation (F=64) ----------------
__global__ void k_gcn2_agg(const float* __restrict__ h, const int* __restrict__ off,
                           const int* __restrict__ deg, const int* __restrict__ srcs,
                           const float* __restrict__ inv, const float* __restrict__ bias,
                           float* __restrict__ out, int n)
{
    int gid = blockIdx.x * blockDim.x + threadIdx.x;
    int d = gid >> 5, lane = gid & 31;
    if (d >= n) return;
    int beg = off[d], end = beg + deg[d];
    float invd = inv[d];

    float2 sv = *(const float2*)(h + (size_t)d * 64 + lane * 2);
    float cs = invd * invd;
    float2 acc = make_float2(sv.x * cs, sv.y * cs);

    int i = beg;
    for (; i + 2 <= end; i += 2) {
        int s0 = srcs[i], s1 = srcs[i + 1];
        float c0 = inv[s0] * invd, c1 = inv[s1] * invd;
        float2 v0 = *(const float2*)(h + (size_t)s0 * 64 + lane * 2);
        float2 v1 = *(const float2*)(h + (size_t)s1 * 64 + lane * 2);
        acc.x += v0.x * c0 + v1.x * c1;
        acc.y += v0.y * c0 + v1.y * c1;
    }
    if (i < end) {
        int s = srcs[i];
        float c = inv[s] * invd;
        float2 v = *(const float2*)(h + (size_t)s * 64 + lane * 2);
        acc.x += v.x * c; acc.y += v.y * c;
    }
    float2 b = *(const float2*)&bias[lane * 2];
    *(float2*)(out + (size_t)d * 64 + lane * 2) = make_float2(acc.x + b.x, acc.y + b.y);
}

// ---------------- host ----------------
static inline int up(int a, int b) { return (a + b - 1) / b; }

extern "C" void kernel_launch(void* const* d_in, const int* in_sizes, int n_in,
                              void* d_out, int out_size)
{
    const float* x       = (const float*)d_in[0];
    const int*   ei      = (const int*)d_in[1];    // int32 (JAX x64 disabled)
    const float* W1      = (const float*)d_in[2];
    const float* b1      = (const float*)d_in[3];
    const float* Wg      = (const float*)d_in[4];
    const float* att_src = (const float*)d_in[5];
    const float* att_dst = (const float*)d_in[6];
    const float* bg      = (const float*)d_in[7];
    const float* W3      = (const float*)d_in[8];
    const float* b3      = (const float*)d_in[9];
    float* out = (float*)d_out;

    int n = in_sizes[0] / 128;
    int E = in_sizes[1] / 2;
    const int* src = ei;
    const int* dst = ei + E;

    void* p;
    cudaGetSymbolAddress(&p, g_h1);   float* h1    = (float*)p;
    cudaGetSymbolAddress(&p, g_agg);  float* agg   = (float*)p;
    cudaGetSymbolAddress(&p, g_inv);  float* inv   = (float*)p;
    cudaGetSymbolAddress(&p, g_as);   float* as_   = (float*)p;
    cudaGetSymbolAddress(&p, g_ad);   float* ad_   = (float*)p;
    cudaGetSymbolAddress(&p, g_hx);   float* hx    = (float*)p;
    cudaGetSymbolAddress(&p, g_h3);   float* h3    = (float*)p;
    cudaGetSymbolAddress(&p, g_deg);  int*   deg   = (int*)p;
    cudaGetSymbolAddress(&p, g_off);  int*   off   = (int*)p;
    cudaGetSymbolAddress(&p, g_cur);  int*   cur   = (int*)p;
    cudaGetSymbolAddress(&p, g_srcs); int*   srcs  = (int*)p;
    cudaGetSymbolAddress(&p, g_total); unsigned* total = (unsigned*)p;

    const int T = 256;

    // CSR build
    k_zero_deg <<<up(n, T), T>>>(deg, total, n);
    k_deg_count<<<up(E, T), T>>>(dst, deg, E);
    k_inv      <<<up(n, T), T>>>(deg, inv, n);
    k_offsets  <<<up(n, T), T>>>(deg, off, cur, total, n);
    k_fill     <<<up(E, T), T>>>(src, dst, cur, srcs, E);

    // ---- GCN layer 1 ----
    gemm_tf32<128,128><<<up(n, 128), 256>>>(x, W1, h1, n);
    k_gcn1_agg<<<up(n * 32, T), T>>>(h1, off, deg, srcs, inv, b1, agg, n);

    // ---- GAT layer ----
    gemm_tf32<128,128><<<up(n, 128), 256>>>(agg, Wg, h1, n);   // h2 in h1
    k_gat_scores<<<up(n * 64, T), T>>>(h1, att_src, att_dst, as_, ad_, n);
    k_gat_agg   <<<up(n * 32, T), T>>>(h1, off, deg, srcs, as_, ad_, bg, hx, n);

    // ---- GCN layer 2 ----
    gemm_tf32<64,64><<<up(n, 128), 256>>>(hx, W3, h3, n);
    k_gcn2_agg<<<up(n * 32, T), T>>>(h3, off, deg, srcs, inv, b3, out, n);
}

// round 7
// speedup vs baseline: 3.7427x; 1.0977x over previous
#include <cuda_runtime.h>
#include <cstdint>

// ---------------- scratch (device globals; no allocation) ----------------
#define NMAX 50000
#define EMAX 800000
__device__ float g_h1 [NMAX * 128];   // x@W1, later h2 (GAT transform)
__device__ float g_agg[NMAX * 128];   // relu(GCN1) output
__device__ float g_inv[NMAX];         // rsqrt(deg)
__device__ float g_as [NMAX * 2];     // GAT a_src per (node, head)
__device__ float g_ad [NMAX * 2];     // GAT a_dst per (node, head)
__device__ float g_hx [NMAX * 64];    // elu(mean-head GAT) = GCN2 input
__device__ float g_h3 [NMAX * 64];    // hx @ W3
__device__ int   g_deg[NMAX];
__device__ int   g_off[NMAX];
__device__ int   g_cur[NMAX];
__device__ int   g_srcs[EMAX];        // src ids bucketed by dst
__device__ unsigned g_total;

__device__ __forceinline__ float leaky(float v) { return v > 0.f ? v : 0.2f * v; }

// ---------------- degree + CSR build ----------------
__global__ void k_zero_deg(int* deg, unsigned* total, int n) {
    int i = blockIdx.x * blockDim.x + threadIdx.x;
    if (i < n) deg[i] = 0;
    if (i == 0) *total = 0u;
}
__global__ void k_deg_count(const int* __restrict__ dst, int* deg, int E) {
    int i = blockIdx.x * blockDim.x + threadIdx.x;
    if (i < E) atomicAdd(&deg[dst[i]], 1);
}
// offsets via warp-scan + one atomic per warp; also computes inv = rsqrt(deg+1)
__global__ void k_offsets(const int* __restrict__ deg, int* off, int* cur,
                          float* inv, unsigned* total, int n) {
    int i = blockIdx.x * blockDim.x + threadIdx.x;
    int lane = threadIdx.x & 31;
    int d = (i < n) ? deg[i] : 0;
    int x = d;
    #pragma unroll
    for (int o = 1; o < 32; o <<= 1) {
        int y = __shfl_up_sync(0xffffffffu, x, o);
        if (lane >= o) x += y;
    }
    int wsum = __shfl_sync(0xffffffffu, x, 31);
    unsigned base = 0;
    if (lane == 31) base = atomicAdd(total, (unsigned)wsum);
    base = __shfl_sync(0xffffffffu, base, 31);
    int excl = (int)base + x - d;
    if (i < n) {
        off[i] = excl; cur[i] = excl;
        inv[i] = rsqrtf((float)(d + 1));
    }
}
__global__ void k_fill(const int* __restrict__ src, const int* __restrict__ dst,
                       int* cur, int* srcs, int E) {
    int i = blockIdx.x * blockDim.x + threadIdx.x;
    if (i >= E) return;
    int pos = atomicAdd(&cur[dst[i]], 1);
    srcs[pos] = src[i];
}

// ---------------- TF32 tensor-core GEMM with error compensation ----------------
__device__ __forceinline__ void split_tf32(float x, uint32_t& hi, uint32_t& lo) {
    uint32_t h;
    asm("cvt.rna.tf32.f32 %0, %1;" : "=r"(h) : "f"(x));
    float l = x - __uint_as_float(h);
    uint32_t lw;
    asm("cvt.rna.tf32.f32 %0, %1;" : "=r"(lw) : "f"(l));
    hi = h; lo = lw;
}
__device__ __forceinline__ void mma_tf32(float* c, const uint32_t* a, const uint32_t* b) {
    asm volatile("mma.sync.aligned.m16n8k8.row.col.f32.tf32.tf32.f32 "
        "{%0,%1,%2,%3},{%4,%5,%6,%7},{%8,%9},{%0,%1,%2,%3};"
        : "+f"(c[0]), "+f"(c[1]), "+f"(c[2]), "+f"(c[3])
        : "r"(a[0]), "r"(a[1]), "r"(a[2]), "r"(a[3]), "r"(b[0]), "r"(b[1]));
}

template<int K, int P>
__global__ void __launch_bounds__(256)
gemm_tf32(const float* __restrict__ X, const float* __restrict__ W,
          float* __restrict__ Y, int n)
{
    constexpr int BM = 128;
    constexpr int BK = 32;
    constexpr int WARPS_N = P / 64;
    constexpr int WARPS_M = 8 / WARPS_N;
    constexpr int WM = BM / WARPS_M;
    constexpr int MF = WM / 16;
    constexpr int NF = 8;
    constexpr int XS = BK + 4;
    constexpr int WS = P + 8;

    __shared__ __align__(16) float Xs[BM * XS];
    __shared__ __align__(16) float Ws[BK * WS];

    int tid = threadIdx.x;
    int wid = tid >> 5, lane = tid & 31;
    int wm = wid % WARPS_M, wn = wid / WARPS_M;
    int g = lane >> 2, tg = lane & 3;

    int r0 = blockIdx.x * BM;
    int rows = n - r0; if (rows > BM) rows = BM;

    float c[MF][NF][4];
    #pragma unroll
    for (int mf = 0; mf < MF; mf++)
        #pragma unroll
        for (int nf = 0; nf < NF; nf++)
            #pragma unroll
            for (int q = 0; q < 4; q++) c[mf][nf][q] = 0.f;

    for (int kt = 0; kt < K; kt += BK) {
        #pragma unroll
        for (int i = tid; i < BK * P / 4; i += 256) {
            int k = i / (P / 4), c4 = (i % (P / 4)) * 4;
            *(float4*)&Ws[k * WS + c4] = *(const float4*)&W[(kt + k) * P + c4];
        }
        #pragma unroll
        for (int i = tid; i < BM * BK / 4; i += 256) {
            int r = i / (BK / 4), k4 = (i % (BK / 4)) * 4;
            float4 v = (r < rows) ? *(const float4*)&X[(size_t)(r0 + r) * K + kt + k4]
                                  : make_float4(0.f, 0.f, 0.f, 0.f);
            *(float4*)&Xs[r * XS + k4] = v;
        }
        __syncthreads();
        #pragma unroll
        for (int k8 = 0; k8 < BK; k8 += 8) {
            uint32_t ah[MF][4], al[MF][4];
            #pragma unroll
            for (int mf = 0; mf < MF; mf++) {
                int rb = wm * WM + mf * 16;
                split_tf32(Xs[(rb + g    ) * XS + k8 + tg    ], ah[mf][0], al[mf][0]);
                split_tf32(Xs[(rb + g + 8) * XS + k8 + tg    ], ah[mf][1], al[mf][1]);
                split_tf32(Xs[(rb + g    ) * XS + k8 + tg + 4], ah[mf][2], al[mf][2]);
                split_tf32(Xs[(rb + g + 8) * XS + k8 + tg + 4], ah[mf][3], al[mf][3]);
            }
            uint32_t bh[NF][2], bl[NF][2];
            #pragma unroll
            for (int nf = 0; nf < NF; nf++) {
                int col = wn * 64 + nf * 8 + g;
                split_tf32(Ws[(k8 + tg    ) * WS + col], bh[nf][0], bl[nf][0]);
                split_tf32(Ws[(k8 + tg + 4) * WS + col], bh[nf][1], bl[nf][1]);
            }
            #pragma unroll
            for (int mf = 0; mf < MF; mf++)
                #pragma unroll
                for (int nf = 0; nf < NF; nf++) {
                    mma_tf32(c[mf][nf], ah[mf], bh[nf]);
                    mma_tf32(c[mf][nf], ah[mf], bl[nf]);
                    mma_tf32(c[mf][nf], al[mf], bh[nf]);
                }
        }
        __syncthreads();
    }
    #pragma unroll
    for (int mf = 0; mf < MF; mf++) {
        int rb = wm * WM + mf * 16;
        #pragma unroll
        for (int nf = 0; nf < NF; nf++) {
            int col = wn * 64 + nf * 8 + 2 * tg;
            int ra = rb + g, rc = rb + g + 8;
            if (ra < rows)
                *(float2*)&Y[(size_t)(r0 + ra) * P + col] = make_float2(c[mf][nf][0], c[mf][nf][1]);
            if (rc < rows)
                *(float2*)&Y[(size_t)(r0 + rc) * P + col] = make_float2(c[mf][nf][2], c[mf][nf][3]);
        }
    }
}

// ---------------- GCN1 pull-aggregation (F=128) + relu, unroll-4 ----------------
__global__ void k_gcn1_agg(const float* __restrict__ h, const int* __restrict__ off,
                           const int* __restrict__ deg, const int* __restrict__ srcs,
                           const float* __restrict__ inv, const float* __restrict__ bias,
                           float* __restrict__ out, int n)
{
    int gid = blockIdx.x * blockDim.x + threadIdx.x;
    int d = gid >> 5, lane = gid & 31;
    if (d >= n) return;
    int beg = off[d], end = beg + deg[d];
    float invd = inv[d];

    float4 sv = *(const float4*)(h + (size_t)d * 128 + lane * 4);
    float cs = invd * invd;
    float4 acc = make_float4(sv.x * cs, sv.y * cs, sv.z * cs, sv.w * cs);

    int i = beg;
    for (; i + 4 <= end; i += 4) {
        int s0 = srcs[i], s1 = srcs[i+1], s2 = srcs[i+2], s3 = srcs[i+3];
        float c0 = inv[s0] * invd, c1 = inv[s1] * invd;
        float c2 = inv[s2] * invd, c3 = inv[s3] * invd;
        float4 v0 = *(const float4*)(h + (size_t)s0 * 128 + lane * 4);
        float4 v1 = *(const float4*)(h + (size_t)s1 * 128 + lane * 4);
        float4 v2 = *(const float4*)(h + (size_t)s2 * 128 + lane * 4);
        float4 v3 = *(const float4*)(h + (size_t)s3 * 128 + lane * 4);
        acc.x += v0.x*c0 + v1.x*c1 + v2.x*c2 + v3.x*c3;
        acc.y += v0.y*c0 + v1.y*c1 + v2.y*c2 + v3.y*c3;
        acc.z += v0.z*c0 + v1.z*c1 + v2.z*c2 + v3.z*c3;
        acc.w += v0.w*c0 + v1.w*c1 + v2.w*c2 + v3.w*c3;
    }
    for (; i < end; i++) {
        int s = srcs[i];
        float c = inv[s] * invd;
        float4 v = *(const float4*)(h + (size_t)s * 128 + lane * 4);
        acc.x += v.x * c; acc.y += v.y * c; acc.z += v.z * c; acc.w += v.w * c;
    }
    float4 b = *(const float4*)&bias[lane * 4];
    acc.x = fmaxf(acc.x + b.x, 0.f); acc.y = fmaxf(acc.y + b.y, 0.f);
    acc.z = fmaxf(acc.z + b.z, 0.f); acc.w = fmaxf(acc.w + b.w, 0.f);
    *(float4*)(out + (size_t)d * 128 + lane * 4) = acc;
}

// ---------------- GAT scores ----------------
__global__ void k_gat_scores(const float* __restrict__ h2, const float* __restrict__ att_s,
                             const float* __restrict__ att_d, float* __restrict__ as_,
                             float* __restrict__ ad_, int n)
{
    int gid = blockIdx.x * blockDim.x + threadIdx.x;
    int w = gid >> 5, lane = gid & 31;
    if (w >= n * 2) return;
    int nn = w >> 1, hh = w & 1;
    const float* row = h2 + (size_t)nn * 128 + hh * 64;
    float v0 = row[lane], v1 = row[lane + 32];
    float s = v0 * att_s[hh * 64 + lane] + v1 * att_s[hh * 64 + lane + 32];
    float d = v0 * att_d[hh * 64 + lane] + v1 * att_d[hh * 64 + lane + 32];
    #pragma unroll
    for (int o = 16; o; o >>= 1) {
        s += __shfl_down_sync(0xffffffffu, s, o);
        d += __shfl_down_sync(0xffffffffu, d, o);
    }
    if (lane == 0) { as_[w] = s; ad_[w] = d; }
}

// ---------------- GAT fused softmax + aggregation + head-mean + elu ----------------
__global__ void k_gat_agg(const float* __restrict__ h2, const int* __restrict__ off,
                          const int* __restrict__ deg, const int* __restrict__ srcs,
                          const float* __restrict__ as_, const float* __restrict__ ad_,
                          const float* __restrict__ bg, float* __restrict__ hx, int n)
{
    int gid = blockIdx.x * blockDim.x + threadIdx.x;
    int d = gid >> 5, lane = gid & 31;
    if (d >= n) return;
    int beg = off[d], end = beg + deg[d];

    float2 ad = *(const float2*)(ad_ + d * 2);
    float2 asd = *(const float2*)(as_ + d * 2);
    float e0s = leaky(asd.x + ad.x), e1s = leaky(asd.y + ad.y);

    float m0 = e0s, m1 = e1s;
    for (int i = beg + lane; i < end; i += 32) {
        float2 a = *(const float2*)(as_ + srcs[i] * 2);
        m0 = fmaxf(m0, leaky(a.x + ad.x));
        m1 = fmaxf(m1, leaky(a.y + ad.y));
    }
    #pragma unroll
    for (int o = 16; o; o >>= 1) {
        m0 = fmaxf(m0, __shfl_xor_sync(0xffffffffu, m0, o));
        m1 = fmaxf(m1, __shfl_xor_sync(0xffffffffu, m1, o));
    }
    float den0 = 0.f, den1 = 0.f;
    for (int i = beg + lane; i < end; i += 32) {
        float2 a = *(const float2*)(as_ + srcs[i] * 2);
        den0 += __expf(leaky(a.x + ad.x) - m0);
        den1 += __expf(leaky(a.y + ad.y) - m1);
    }
    #pragma unroll
    for (int o = 16; o; o >>= 1) {
        den0 += __shfl_xor_sync(0xffffffffu, den0, o);
        den1 += __shfl_xor_sync(0xffffffffu, den1, o);
    }
    den0 += __expf(e0s - m0);
    den1 += __expf(e1s - m1);
    float r0 = __fdividef(1.f, den0), r1 = __fdividef(1.f, den1);

    float als = (lane < 16) ? __expf(e0s - m0) * r0 : __expf(e1s - m1) * r1;
    float4 sv = *(const float4*)(h2 + (size_t)d * 128 + lane * 4);
    float4 acc = make_float4(sv.x * als, sv.y * als, sv.z * als, sv.w * als);
    int i = beg;
    for (; i + 4 <= end; i += 4) {
        int s0 = srcs[i], s1 = srcs[i+1], s2 = srcs[i+2], s3 = srcs[i+3];
        float2 a0 = *(const float2*)(as_ + s0 * 2);
        float2 a1 = *(const float2*)(as_ + s1 * 2);
        float2 a2 = *(const float2*)(as_ + s2 * 2);
        float2 a3 = *(const float2*)(as_ + s3 * 2);
        bool h0 = lane < 16;
        float c0 = h0 ? __expf(leaky(a0.x + ad.x) - m0) * r0 : __expf(leaky(a0.y + ad.y) - m1) * r1;
        float c1 = h0 ? __expf(leaky(a1.x + ad.x) - m0) * r0 : __expf(leaky(a1.y + ad.y) - m1) * r1;
        float c2 = h0 ? __expf(leaky(a2.x + ad.x) - m0) * r0 : __expf(leaky(a2.y + ad.y) - m1) * r1;
        float c3 = h0 ? __expf(leaky(a3.x + ad.x) - m0) * r0 : __expf(leaky(a3.y + ad.y) - m1) * r1;
        float4 v0 = *(const float4*)(h2 + (size_t)s0 * 128 + lane * 4);
        float4 v1 = *(const float4*)(h2 + (size_t)s1 * 128 + lane * 4);
        float4 v2 = *(const float4*)(h2 + (size_t)s2 * 128 + lane * 4);
        float4 v3 = *(const float4*)(h2 + (size_t)s3 * 128 + lane * 4);
        acc.x += v0.x*c0 + v1.x*c1 + v2.x*c2 + v3.x*c3;
        acc.y += v0.y*c0 + v1.y*c1 + v2.y*c2 + v3.y*c3;
        acc.z += v0.z*c0 + v1.z*c1 + v2.z*c2 + v3.z*c3;
        acc.w += v0.w*c0 + v1.w*c1 + v2.w*c2 + v3.w*c3;
    }
    for (; i < end; i++) {
        int s = srcs[i];
        float2 a = *(const float2*)(as_ + s * 2);
        float c = (lane < 16) ? __expf(leaky(a.x + ad.x) - m0) * r0
                              : __expf(leaky(a.y + ad.y) - m1) * r1;
        float4 v = *(const float4*)(h2 + (size_t)s * 128 + lane * 4);
        acc.x += v.x * c; acc.y += v.y * c; acc.z += v.z * c; acc.w += v.w * c;
    }
    float ox = __shfl_down_sync(0xffffffffu, acc.x, 16);
    float oy = __shfl_down_sync(0xffffffffu, acc.y, 16);
    float oz = __shfl_down_sync(0xffffffffu, acc.z, 16);
    float ow = __shfl_down_sync(0xffffffffu, acc.w, 16);
    if (lane < 16) {
        float4 b = *(const float4*)&bg[lane * 4];
        float4 r;
        r.x = 0.5f * (acc.x + ox) + b.x;
        r.y = 0.5f * (acc.y + oy) + b.y;
        r.z = 0.5f * (acc.z + oz) + b.z;
        r.w = 0.5f * (acc.w + ow) + b.w;
        r.x = r.x > 0.f ? r.x : expm1f(r.x);
        r.y = r.y > 0.f ? r.y : expm1f(r.y);
        r.z = r.z > 0.f ? r.z : expm1f(r.z);
        r.w = r.w > 0.f ? r.w : expm1f(r.w);
        *(float4*)(hx + (size_t)d * 64 + lane * 4) = r;
    }
}

// ---------------- GCN2 pull-aggregation (F=64), unroll-4 ----------------
__global__ void k_gcn2_agg(const float* __restrict__ h, const int* __restrict__ off,
                           const int* __restrict__ deg, const int* __restrict__ srcs,
                           const float* __restrict__ inv, const float* __restrict__ bias,
                           float* __restrict__ out, int n)
{
    int gid = blockIdx.x * blockDim.x + threadIdx.x;
    int d = gid >> 5, lane = gid & 31;
    if (d >= n) return;
    int beg = off[d], end = beg + deg[d];
    float invd = inv[d];

    float2 sv = *(const float2*)(h + (size_t)d * 64 + lane * 2);
    float cs = invd * invd;
    float2 acc = make_float2(sv.x * cs, sv.y * cs);

    int i = beg;
    for (; i + 4 <= end; i += 4) {
        int s0 = srcs[i], s1 = srcs[i+1], s2 = srcs[i+2], s3 = srcs[i+3];
        float c0 = inv[s0] * invd, c1 = inv[s1] * invd;
        float c2 = inv[s2] * invd, c3 = inv[s3] * invd;
        float2 v0 = *(const float2*)(h + (size_t)s0 * 64 + lane * 2);
        float2 v1 = *(const float2*)(h + (size_t)s1 * 64 + lane * 2);
        float2 v2 = *(const float2*)(h + (size_t)s2 * 64 + lane * 2);
        float2 v3 = *(const float2*)(h + (size_t)s3 * 64 + lane * 2);
        acc.x += v0.x*c0 + v1.x*c1 + v2.x*c2 + v3.x*c3;
        acc.y += v0.y*c0 + v1.y*c1 + v2.y*c2 + v3.y*c3;
    }
    for (; i < end; i++) {
        int s = srcs[i];
        float c = inv[s] * invd;
        float2 v = *(const float2*)(h + (size_t)s * 64 + lane * 2);
        acc.x += v.x * c; acc.y += v.y * c;
    }
    float2 b = *(const float2*)&bias[lane * 2];
    *(float2*)(out + (size_t)d * 64 + lane * 2) = make_float2(acc.x + b.x, acc.y + b.y);
}

// ---------------- host ----------------
static inline int up(int a, int b) { return (a + b - 1) / b; }

extern "C" void kernel_launch(void* const* d_in, const int* in_sizes, int n_in,
                              void* d_out, int out_size)
{
    const float* x       = (const float*)d_in[0];
    const int*   ei      = (const int*)d_in[1];    // int32 (JAX x64 disabled)
    const float* W1      = (const float*)d_in[2];
    const float* b1      = (const float*)d_in[3];
    const float* Wg      = (const float*)d_in[4];
    const float* att_src = (const float*)d_in[5];
    const float* att_dst = (const float*)d_in[6];
    const float* bg      = (const float*)d_in[7];
    const float* W3      = (const float*)d_in[8];
    const float* b3      = (const float*)d_in[9];
    float* out = (float*)d_out;

    int n = in_sizes[0] / 128;
    int E = in_sizes[1] / 2;
    const int* src = ei;
    const int* dst = ei + E;

    void* p;
    cudaGetSymbolAddress(&p, g_h1);   float* h1    = (float*)p;
    cudaGetSymbolAddress(&p, g_agg);  float* agg   = (float*)p;
    cudaGetSymbolAddress(&p, g_inv);  float* inv   = (float*)p;
    cudaGetSymbolAddress(&p, g_as);   float* as_   = (float*)p;
    cudaGetSymbolAddress(&p, g_ad);   float* ad_   = (float*)p;
    cudaGetSymbolAddress(&p, g_hx);   float* hx    = (float*)p;
    cudaGetSymbolAddress(&p, g_h3);   float* h3    = (float*)p;
    cudaGetSymbolAddress(&p, g_deg);  int*   deg   = (int*)p;
    cudaGetSymbolAddress(&p, g_off);  int*   off   = (int*)p;
    cudaGetSymbolAddress(&p, g_cur);  int*   cur   = (int*)p;
    cudaGetSymbolAddress(&p, g_srcs); int*   srcs  = (int*)p;
    cudaGetSymbolAddress(&p, g_total); unsigned* total = (unsigned*)p;

    // fork-join side stream for CSR build (created once; capture-safe pattern)
    static cudaStream_t s2 = nullptr;
    static cudaEvent_t evFork = nullptr, evJoin = nullptr;
    if (!s2) {
        cudaStreamCreateWithFlags(&s2, cudaStreamNonBlocking);
        cudaEventCreateWithFlags(&evFork, cudaEventDisableTiming);
        cudaEventCreateWithFlags(&evJoin, cudaEventDisableTiming);
    }

    const int T = 256;

    // ---- fork: CSR build on s2, GEMM1 on default ----
    cudaEventRecord(evFork, 0);
    cudaStreamWaitEvent(s2, evFork, 0);

    k_zero_deg <<<up(n, T), T, 0, s2>>>(deg, total, n);
    k_deg_count<<<up(E, T), T, 0, s2>>>(dst, deg, E);
    k_offsets  <<<up(n, T), T, 0, s2>>>(deg, off, cur, inv, total, n);
    k_fill     <<<up(E, T), T, 0, s2>>>(src, dst, cur, srcs, E);
    cudaEventRecord(evJoin, s2);

    gemm_tf32<128,128><<<up(n, 128), 256>>>(x, W1, h1, n);

    cudaStreamWaitEvent(0, evJoin, 0);   // join before first aggregation

    // ---- GCN layer 1 ----
    k_gcn1_agg<<<up(n * 32, T), T>>>(h1, off, deg, srcs, inv, b1, agg, n);

    // ---- GAT layer ----
    gemm_tf32<128,128><<<up(n, 128), 256>>>(agg, Wg, h1, n);   // h2 in h1
    k_gat_scores<<<up(n * 64, T), T>>>(h1, att_src, att_dst, as_, ad_, n);
    k_gat_agg   <<<up(n * 32, T), T>>>(h1, off, deg, srcs, as_, ad_, bg, hx, n);

    // ---- GCN layer 2 ----
    gemm_tf32<64,64><<<up(n, 128), 256>>>(hx, W3, h3, n);
    k_gcn2_agg<<<up(n * 32, T), T>>>(h3, off, deg, srcs, inv, b3, out, n);
}